// round 3
// baseline (speedup 1.0000x reference)
#include <cuda_runtime.h>

#define NN 50000
#define EE 600000
#define LLM 640
#define HID 128
#define PO 112
#define SD 16

typedef unsigned long long ull;

__device__ __forceinline__ void fma2(ull& acc, ull a, ull b) {
    asm("fma.rn.f32x2 %0, %1, %2, %0;" : "+l"(acc) : "l"(a), "l"(b));
}
__device__ __forceinline__ float2 unpack2(ull v) {
    float2 r;
    asm("mov.b64 {%0,%1}, %2;" : "=f"(r.x), "=f"(r.y) : "l"(v));
    return r;
}

// ---------------- scratch (static device globals; no allocation) ------------
__device__ float g_x[(size_t)NN * HID];     // node features [N,128]
__device__ float g_xw[(size_t)NN * HID];    // x @ W per layer [N,128]
__device__ float g_dis[NN];                 // deg^{-1/2}
__device__ int   g_cnt[NN];                 // in-degree counts
__device__ int   g_rowptr[NN + 1];          // CSR row pointers (by dst)
__device__ int   g_pos[NN];                 // fill cursors
__device__ int   g_col[EE];                 // CSR column indices (src)

// ---------------- CSR build -------------------------------------------------
__global__ void zero_cnt_k() {
    int i = blockIdx.x * blockDim.x + threadIdx.x;
    if (i < NN) g_cnt[i] = 0;
}

__global__ void count_k(const int* __restrict__ dst) {
    int e = blockIdx.x * blockDim.x + threadIdx.x;
    if (e < EE) atomicAdd(&g_cnt[dst[e]], 1);
}

// Single-block scan: rowptr, pos, dis.
__global__ void scan_k() {
    __shared__ int warp_tot[32];
    __shared__ int carry_s;
    int tid = threadIdx.x, lane = tid & 31, w = tid >> 5;
    if (tid == 0) { carry_s = 0; g_rowptr[0] = 0; }
    __syncthreads();
    for (int base = 0; base < NN; base += 1024) {
        int i = base + tid;
        int v = (i < NN) ? g_cnt[i] : 0;
        int x = v;
        #pragma unroll
        for (int o = 1; o < 32; o <<= 1) {
            int y = __shfl_up_sync(0xffffffffu, x, o);
            if (lane >= o) x += y;
        }
        if (lane == 31) warp_tot[w] = x;
        __syncthreads();
        if (w == 0) {
            int t = warp_tot[lane];
            #pragma unroll
            for (int o = 1; o < 32; o <<= 1) {
                int y = __shfl_up_sync(0xffffffffu, t, o);
                if (lane >= o) t += y;
            }
            warp_tot[lane] = t;
        }
        __syncthreads();
        int woff = (w > 0) ? warp_tot[w - 1] : 0;
        int incl = x + woff + carry_s;
        if (i < NN) {
            g_rowptr[i + 1] = incl;
            g_pos[i] = incl - v;
            g_dis[i] = rsqrtf(1.0f + (float)v);
        }
        __syncthreads();
        if (tid == 1023) carry_s = incl;
        __syncthreads();
    }
}

__global__ void fill_k(const int* __restrict__ src, const int* __restrict__ dst) {
    int e = blockIdx.x * blockDim.x + threadIdx.x;
    if (e < EE) {
        int p = atomicAdd(&g_pos[dst[e]], 1);
        g_col[p] = src[e];
    }
}

// ---------------- projection GEMM: g_x[:, :112] = llm @ W + b ---------------
// BM=128, BN=112, BK=32, 256 threads, (4 row-pairs)x7 packed f32x2 tile.
// As: column-major [k][m] stride 130 (even, not mult of 8 -> <=2-way STS conflict,
//     LDS.64 row-pairs are warp-broadcast). Bs: duplicated (b,b) float2.
#define AS_S 130
__global__ __launch_bounds__(256, 2) void proj_k(const float* __restrict__ A,
                                                 const float* __restrict__ W,
                                                 const float* __restrict__ bias) {
    __shared__ __align__(16) float  As[32 * AS_S];   // 16.6 KB
    __shared__ __align__(16) float2 Bs[32 * 112];    // 28.7 KB
    int tid = threadIdx.x;
    int tx = tid & 15, ty = tid >> 4;
    int row0 = blockIdx.x * 128;
    ull acc[4][7];
    #pragma unroll
    for (int r = 0; r < 4; r++)
        #pragma unroll
        for (int c = 0; c < 7; c++) acc[r][c] = 0ULL;

    for (int k0 = 0; k0 < LLM; k0 += 32) {
        // A tile: 128 rows x 32 k. Each thread: one float4 along k, scatter to col-major.
        #pragma unroll
        for (int i = 0; i < 4; i++) {
            int f = tid + i * 256;
            int r = f >> 3, c = (f & 7) * 4;     // r = m-row, c = k-offset
            int gr = row0 + r;
            float4 v = make_float4(0.f, 0.f, 0.f, 0.f);
            if (gr < NN) v = *(const float4*)(A + (size_t)gr * LLM + k0 + c);
            As[(c + 0) * AS_S + r] = v.x;
            As[(c + 1) * AS_S + r] = v.y;
            As[(c + 2) * AS_S + r] = v.z;
            As[(c + 3) * AS_S + r] = v.w;
        }
        // B tile duplicated: 32 k x 112 n
        for (int f = tid; f < 896; f += 256) {
            int r = f / 28, c = (f % 28) * 4;
            float4 w = *(const float4*)(W + (size_t)(k0 + r) * 112 + c);
            float4* o = (float4*)(Bs + r * 112 + c);
            o[0] = make_float4(w.x, w.x, w.y, w.y);
            o[1] = make_float4(w.z, w.z, w.w, w.w);
        }
        __syncthreads();
        #pragma unroll
        for (int k = 0; k < 32; k++) {
            ull a[4], bb[7];
            const float* ak = As + k * AS_S + ty * 8;
            #pragma unroll
            for (int r = 0; r < 4; r++) a[r] = *(const ull*)(ak + 2 * r);
            const ull* bk = (const ull*)(Bs + k * 112 + tx * 7);
            #pragma unroll
            for (int c = 0; c < 7; c++) bb[c] = bk[c];
            #pragma unroll
            for (int r = 0; r < 4; r++)
                #pragma unroll
                for (int c = 0; c < 7; c++) fma2(acc[r][c], a[r], bb[c]);
        }
        __syncthreads();
    }
    #pragma unroll
    for (int r = 0; r < 4; r++) {
        int gr0 = row0 + ty * 8 + 2 * r;
        if (gr0 < NN) {
            #pragma unroll
            for (int c = 0; c < 7; c++) {
                int col = tx * 7 + c;
                float2 v = unpack2(acc[r][c]);
                float bv = bias[col];
                g_x[(size_t)gr0 * HID + col] = v.x + bv;
                if (gr0 + 1 < NN) g_x[(size_t)(gr0 + 1) * HID + col] = v.y + bv;
            }
        }
    }
}

// ---------------- struct embedding concat: g_x[:, 112:128] -----------------
__global__ void struct_k(const int* __restrict__ ids, const float* __restrict__ emb) {
    int idx = blockIdx.x * blockDim.x + threadIdx.x;
    if (idx < NN * SD) {
        int i = idx >> 4, t = idx & 15;
        g_x[(size_t)i * HID + PO + t] = emb[ids[i] * SD + t];
    }
}

// ---------------- GCN GEMM: g_xw = g_x @ W (128x128) ------------------------
// BM=128, BN=128, BK=16, 256 threads, (4 row-pairs)x8 packed f32x2 tile.
#define AS2_S 130
__global__ __launch_bounds__(256, 2) void gemm_k(const float* __restrict__ W) {
    __shared__ __align__(16) float  As[16 * AS2_S];  // 8.3 KB
    __shared__ __align__(16) float2 Bs[16 * 128];    // 16 KB
    int tid = threadIdx.x;
    int tx = tid & 15, ty = tid >> 4;
    int row0 = blockIdx.x * 128;
    ull acc[4][8];
    #pragma unroll
    for (int r = 0; r < 4; r++)
        #pragma unroll
        for (int c = 0; c < 8; c++) acc[r][c] = 0ULL;

    for (int k0 = 0; k0 < HID; k0 += 16) {
        // A tile: 128 x 16, col-major scatter
        #pragma unroll
        for (int i = 0; i < 2; i++) {
            int f = tid + i * 256;
            int r = f >> 2, c = (f & 3) * 4;
            int gr = row0 + r;
            float4 v = make_float4(0.f, 0.f, 0.f, 0.f);
            if (gr < NN) v = *(const float4*)(g_x + (size_t)gr * HID + k0 + c);
            As[(c + 0) * AS2_S + r] = v.x;
            As[(c + 1) * AS2_S + r] = v.y;
            As[(c + 2) * AS2_S + r] = v.z;
            As[(c + 3) * AS2_S + r] = v.w;
        }
        // B tile duplicated: 16 x 128
        #pragma unroll
        for (int i = 0; i < 2; i++) {
            int f = tid + i * 256;
            int r = f >> 5, c = (f & 31) * 4;
            float4 w = *(const float4*)(W + (size_t)(k0 + r) * 128 + c);
            float4* o = (float4*)(Bs + r * 128 + c);
            o[0] = make_float4(w.x, w.x, w.y, w.y);
            o[1] = make_float4(w.z, w.z, w.w, w.w);
        }
        __syncthreads();
        #pragma unroll
        for (int k = 0; k < 16; k++) {
            ull a[4], bb[8];
            const float* ak = As + k * AS2_S + ty * 8;
            #pragma unroll
            for (int r = 0; r < 4; r++) a[r] = *(const ull*)(ak + 2 * r);
            const ull* bk = (const ull*)(Bs + k * 128 + tx * 8);
            #pragma unroll
            for (int c = 0; c < 8; c++) bb[c] = bk[c];
            #pragma unroll
            for (int r = 0; r < 4; r++)
                #pragma unroll
                for (int c = 0; c < 8; c++) fma2(acc[r][c], a[r], bb[c]);
        }
        __syncthreads();
    }
    #pragma unroll
    for (int r = 0; r < 4; r++) {
        int gr0 = row0 + ty * 8 + 2 * r;
        if (gr0 >= NN) continue;
        float2 v[8];
        #pragma unroll
        for (int c = 0; c < 8; c++) v[c] = unpack2(acc[r][c]);
        float4* out0 = (float4*)(g_xw + (size_t)gr0 * HID + tx * 8);
        out0[0] = make_float4(v[0].x, v[1].x, v[2].x, v[3].x);
        out0[1] = make_float4(v[4].x, v[5].x, v[6].x, v[7].x);
        if (gr0 + 1 < NN) {
            float4* out1 = (float4*)(g_xw + (size_t)(gr0 + 1) * HID + tx * 8);
            out1[0] = make_float4(v[0].y, v[1].y, v[2].y, v[3].y);
            out1[1] = make_float4(v[4].y, v[5].y, v[6].y, v[7].y);
        }
    }
}

// ---------------- aggregation + self-loop + bias + relu + residual ----------
__global__ void agg_k(const float* __restrict__ bias) {
    int warp = threadIdx.x >> 5, lane = threadIdx.x & 31;
    int row = blockIdx.x * 8 + warp;
    if (row >= NN) return;
    const float4* xw4 = (const float4*)g_xw;
    float4 acc = make_float4(0.f, 0.f, 0.f, 0.f);
    int e = g_rowptr[row], end = g_rowptr[row + 1];
    for (; e < end; e++) {
        int s = g_col[e];
        float w = g_dis[s];
        float4 v = xw4[(size_t)s * 32 + lane];
        acc.x += w * v.x; acc.y += w * v.y; acc.z += w * v.z; acc.w += w * v.w;
    }
    float d = g_dis[row];
    float dd = d * d;
    float4 sv = xw4[(size_t)row * 32 + lane];
    float4 bb = ((const float4*)bias)[lane];
    float4 r;
    r.x = fmaxf(d * acc.x + dd * sv.x + bb.x, 0.f);
    r.y = fmaxf(d * acc.y + dd * sv.y + bb.y, 0.f);
    r.z = fmaxf(d * acc.z + dd * sv.z + bb.z, 0.f);
    r.w = fmaxf(d * acc.w + dd * sv.w + bb.w, 0.f);
    float4* x4 = (float4*)g_x;
    float4 xo = x4[(size_t)row * 32 + lane];
    xo.x += r.x; xo.y += r.y; xo.z += r.z; xo.w += r.w;
    x4[(size_t)row * 32 + lane] = xo;
}

// ---------------- final LayerNorm -> d_out ----------------------------------
__global__ void ln_k(const float* __restrict__ g, const float* __restrict__ b,
                     float* __restrict__ out) {
    int warp = threadIdx.x >> 5, lane = threadIdx.x & 31;
    int row = blockIdx.x * 8 + warp;
    if (row >= NN) return;
    float4 v = ((const float4*)g_x)[(size_t)row * 32 + lane];
    float s = v.x + v.y + v.z + v.w;
    float s2 = v.x * v.x + v.y * v.y + v.z * v.z + v.w * v.w;
    #pragma unroll
    for (int o = 16; o; o >>= 1) {
        s  += __shfl_xor_sync(0xffffffffu, s, o);
        s2 += __shfl_xor_sync(0xffffffffu, s2, o);
    }
    float mean = s * (1.0f / 128.0f);
    float var = s2 * (1.0f / 128.0f) - mean * mean;
    float rstd = rsqrtf(var + 1e-5f);
    float4 gg = ((const float4*)g)[lane];
    float4 bb = ((const float4*)b)[lane];
    float4 o4;
    o4.x = (v.x - mean) * rstd * gg.x + bb.x;
    o4.y = (v.y - mean) * rstd * gg.y + bb.y;
    o4.z = (v.z - mean) * rstd * gg.z + bb.z;
    o4.w = (v.w - mean) * rstd * gg.w + bb.w;
    ((float4*)out)[(size_t)row * 32 + lane] = o4;
}

// ---------------- launcher --------------------------------------------------
extern "C" void kernel_launch(void* const* d_in, const int* in_sizes, int n_in,
                              void* d_out, int out_size) {
    const float* llm = (const float*)d_in[0];
    const int*   ids = (const int*)d_in[1];
    const int*   ei  = (const int*)d_in[2];
    const float* pW  = (const float*)d_in[3];
    const float* pb  = (const float*)d_in[4];
    const float* emb = (const float*)d_in[5];
    const float* gW  = (const float*)d_in[6];
    const float* gb  = (const float*)d_in[7];
    const float* lg  = (const float*)d_in[8];
    const float* lb  = (const float*)d_in[9];
    const int* src = ei;
    const int* dst = ei + EE;

    const int MB = (NN + 127) / 128;
    const int WB = (NN + 7) / 8;

    zero_cnt_k<<<(NN + 255) / 256, 256>>>();
    count_k<<<(EE + 255) / 256, 256>>>(dst);
    scan_k<<<1, 1024>>>();
    fill_k<<<(EE + 255) / 256, 256>>>(src, dst);

    proj_k<<<MB, 256>>>(llm, pW, pb);
    struct_k<<<(NN * SD + 255) / 256, 256>>>(ids, emb);

    for (int l = 0; l < 2; l++) {
        gemm_k<<<MB, 256>>>(gW + (size_t)l * HID * HID);
        agg_k<<<WB, 256>>>(gb + (size_t)l * HID);
    }
    ln_k<<<WB, 256>>>(lg, lb, (float*)d_out);
}

// round 5
// speedup vs baseline: 1.3408x; 1.3408x over previous
#include <cuda_runtime.h>

#define NN 50000
#define EE 600000
#define LLM 640
#define HID 128
#define PO 112
#define SD 16

typedef unsigned int uint;

// ---------------- scratch (static device globals; no allocation) ------------
__device__ float g_x[(size_t)NN * HID];     // node features [N,128]
__device__ float g_xw[(size_t)NN * HID];    // x @ W per layer [N,128]
__device__ float g_dis[NN];                 // deg^{-1/2}
__device__ int   g_cnt[NN];                 // in-degree counts
__device__ int   g_rowptr[NN + 1];          // CSR row pointers (by dst)
__device__ int   g_pos[NN];                 // fill cursors
__device__ int   g_col[EE];                 // CSR column indices (src)
__device__ float g_Wp[(size_t)LLM * HID];   // proj_W padded to 128 cols
__device__ float g_bp[HID];                 // proj bias padded

__device__ __forceinline__ uint f2tf32(float x) {
    uint r;
    asm("cvt.rna.tf32.f32 %0, %1;" : "=r"(r) : "f"(x));
    return r;
}

// ---------------- CSR build -------------------------------------------------
__global__ void zero_cnt_k() {
    int i = blockIdx.x * blockDim.x + threadIdx.x;
    if (i < NN) g_cnt[i] = 0;
}

__global__ void count_k(const int* __restrict__ dst) {
    int e = blockIdx.x * blockDim.x + threadIdx.x;
    if (e < EE) atomicAdd(&g_cnt[dst[e]], 1);
}

__global__ void scan_k() {
    __shared__ int warp_tot[32];
    __shared__ int carry_s;
    int tid = threadIdx.x, lane = tid & 31, w = tid >> 5;
    if (tid == 0) { carry_s = 0; g_rowptr[0] = 0; }
    __syncthreads();
    for (int base = 0; base < NN; base += 1024) {
        int i = base + tid;
        int v = (i < NN) ? g_cnt[i] : 0;
        int x = v;
        #pragma unroll
        for (int o = 1; o < 32; o <<= 1) {
            int y = __shfl_up_sync(0xffffffffu, x, o);
            if (lane >= o) x += y;
        }
        if (lane == 31) warp_tot[w] = x;
        __syncthreads();
        if (w == 0) {
            int t = warp_tot[lane];
            #pragma unroll
            for (int o = 1; o < 32; o <<= 1) {
                int y = __shfl_up_sync(0xffffffffu, t, o);
                if (lane >= o) t += y;
            }
            warp_tot[lane] = t;
        }
        __syncthreads();
        int woff = (w > 0) ? warp_tot[w - 1] : 0;
        int incl = x + woff + carry_s;
        if (i < NN) {
            g_rowptr[i + 1] = incl;
            g_pos[i] = incl - v;
            g_dis[i] = rsqrtf(1.0f + (float)v);
        }
        __syncthreads();
        if (tid == 1023) carry_s = incl;
        __syncthreads();
    }
}

__global__ void fill_k(const int* __restrict__ src, const int* __restrict__ dst) {
    int e = blockIdx.x * blockDim.x + threadIdx.x;
    if (e < EE) {
        int p = atomicAdd(&g_pos[dst[e]], 1);
        g_col[p] = src[e];
    }
}

// ---------------- pad proj_W [640,112] -> g_Wp [640,128], pb -> g_bp --------
__global__ void pad_k(const float* __restrict__ pW, const float* __restrict__ pb) {
    int i = blockIdx.x * blockDim.x + threadIdx.x;
    if (i < LLM * HID) {
        int r = i >> 7, c = i & 127;
        g_Wp[i] = (c < PO) ? pW[r * PO + c] : 0.0f;
    }
    if (i < HID) g_bp[i] = (i < PO) ? pb[i] : 0.0f;
}

// ---------------- tf32 mma GEMM: out[N,128] = A[N,K] @ W[K,128] (+bias) ----
// BM=128, BN=128, BK=32. 8 warps (2 m x 4 n), warp tile 64x32 = 4x4 m16n8k8.
// Smem holds tf32 fragments pre-swizzled: mainloop = LDS.128/LDS.64 + HMMA.
template<int K, int LDA, bool BIAS>
__global__ __launch_bounds__(256, 2) void mma_gemm_k(const float* __restrict__ A,
                                                     const float* __restrict__ W,
                                                     const float* __restrict__ bias,
                                                     float* __restrict__ out) {
    // As[((mtile*4 + k8)*32 + t)*4 + j]   mtile 0..7, k8 0..3
    // Bs[((ntile*4 + k8)*32 + t)*2 + j]   ntile 0..15
    __shared__ __align__(16) uint As[4096];   // 16 KB
    __shared__ __align__(16) uint Bs[4096];   // 16 KB
    int tid = threadIdx.x;
    int lane = tid & 31, wid = tid >> 5;
    int warp_m = wid >> 2;          // 0..1  (64 rows)
    int warp_n = wid & 3;           // 0..3  (32 cols)
    int row0 = blockIdx.x * 128;

    float acc[4][4][4];
    #pragma unroll
    for (int mt = 0; mt < 4; mt++)
        #pragma unroll
        for (int nt = 0; nt < 4; nt++)
            #pragma unroll
            for (int j = 0; j < 4; j++) acc[mt][nt][j] = 0.0f;

    for (int k0 = 0; k0 < K; k0 += 32) {
        // ---- stage A: 128 rows x 32 k, convert to tf32, fragment order ----
        #pragma unroll
        for (int i = 0; i < 4; i++) {
            int f = tid + i * 256;
            int r = f >> 3;                 // 0..127
            int c = (f & 7) * 4;            // 0,4,...,28
            int gr = row0 + r;
            float4 v = make_float4(0.f, 0.f, 0.f, 0.f);
            if (gr < NN) v = *(const float4*)(A + (size_t)gr * LDA + k0 + c);
            int mtile = r >> 4, rloc = r & 15;
            int j = (rloc >> 3) + 2 * ((c >> 2) & 1);
            int tb = (rloc & 7) * 4;
            uint* dst = As + (((mtile << 2) + (c >> 3)) << 7) + j;  // *32*4
            dst[(tb + 0) * 4] = f2tf32(v.x);
            dst[(tb + 1) * 4] = f2tf32(v.y);
            dst[(tb + 2) * 4] = f2tf32(v.z);
            dst[(tb + 3) * 4] = f2tf32(v.w);
        }
        // ---- stage B: 32 k x 128 n ----
        #pragma unroll
        for (int i = 0; i < 4; i++) {
            int f = tid + i * 256;
            int kr = f >> 5;                // 0..31
            int c4 = (f & 31) * 4;          // 0,4,...,124
            float4 v = *(const float4*)(W + (size_t)(k0 + kr) * 128 + c4);
            int k8 = kr >> 3, kloc = kr & 7;
            int j = kloc >> 2, km = kloc & 3;
            int ntile = c4 >> 3, nb = c4 & 7;  // 0 or 4
            uint* dst = Bs + (((ntile << 2) + k8) << 6) + j;  // *32*2
            dst[((nb + 0) * 4 + km) * 2] = f2tf32(v.x);
            dst[((nb + 1) * 4 + km) * 2] = f2tf32(v.y);
            dst[((nb + 2) * 4 + km) * 2] = f2tf32(v.z);
            dst[((nb + 3) * 4 + km) * 2] = f2tf32(v.w);
        }
        __syncthreads();

        // ---- mma mainloop over 4 k8 steps ----
        #pragma unroll
        for (int k8 = 0; k8 < 4; k8++) {
            uint4 a[4];
            uint2 b[4];
            #pragma unroll
            for (int mt = 0; mt < 4; mt++)
                a[mt] = *(const uint4*)(As + ((((warp_m * 4 + mt) << 2) + k8) << 7) + lane * 4);
            #pragma unroll
            for (int nt = 0; nt < 4; nt++)
                b[nt] = *(const uint2*)(Bs + ((((warp_n * 4 + nt) << 2) + k8) << 6) + lane * 2);
            #pragma unroll
            for (int mt = 0; mt < 4; mt++)
                #pragma unroll
                for (int nt = 0; nt < 4; nt++) {
                    asm volatile(
                        "mma.sync.aligned.m16n8k8.row.col.f32.tf32.tf32.f32 "
                        "{%0,%1,%2,%3}, {%4,%5,%6,%7}, {%8,%9}, {%0,%1,%2,%3};"
                        : "+f"(acc[mt][nt][0]), "+f"(acc[mt][nt][1]),
                          "+f"(acc[mt][nt][2]), "+f"(acc[mt][nt][3])
                        : "r"(a[mt].x), "r"(a[mt].y), "r"(a[mt].z), "r"(a[mt].w),
                          "r"(b[nt].x), "r"(b[nt].y));
                }
        }
        __syncthreads();
    }

    // ---- epilogue ----
    #pragma unroll
    for (int mt = 0; mt < 4; mt++) {
        int gr0 = row0 + warp_m * 64 + mt * 16 + (lane >> 2);
        #pragma unroll
        for (int nt = 0; nt < 4; nt++) {
            int col = warp_n * 32 + nt * 8 + (lane & 3) * 2;
            float b0 = 0.f, b1 = 0.f;
            if (BIAS) { b0 = bias[col]; b1 = bias[col + 1]; }
            if (gr0 < NN)
                *(float2*)(out + (size_t)gr0 * 128 + col) =
                    make_float2(acc[mt][nt][0] + b0, acc[mt][nt][1] + b1);
            if (gr0 + 8 < NN)
                *(float2*)(out + (size_t)(gr0 + 8) * 128 + col) =
                    make_float2(acc[mt][nt][2] + b0, acc[mt][nt][3] + b1);
        }
    }
}

// ---------------- struct embedding concat: g_x[:, 112:128] -----------------
__global__ void struct_k(const int* __restrict__ ids, const float* __restrict__ emb) {
    int idx = blockIdx.x * blockDim.x + threadIdx.x;
    if (idx < NN * SD) {
        int i = idx >> 4, t = idx & 15;
        g_x[(size_t)i * HID + PO + t] = emb[ids[i] * SD + t];
    }
}

// ---------------- aggregation + self-loop + bias + relu + residual ----------
__global__ void agg_k(const float* __restrict__ bias) {
    int warp = threadIdx.x >> 5, lane = threadIdx.x & 31;
    int row = blockIdx.x * 8 + warp;
    if (row >= NN) return;
    const float4* xw4 = (const float4*)g_xw;
    float4 acc = make_float4(0.f, 0.f, 0.f, 0.f);
    int e = g_rowptr[row], end = g_rowptr[row + 1];
    for (; e < end; e++) {
        int s = g_col[e];
        float w = g_dis[s];
        float4 v = xw4[(size_t)s * 32 + lane];
        acc.x += w * v.x; acc.y += w * v.y; acc.z += w * v.z; acc.w += w * v.w;
    }
    float d = g_dis[row];
    float dd = d * d;
    float4 sv = xw4[(size_t)row * 32 + lane];
    float4 bb = ((const float4*)bias)[lane];
    float4 r;
    r.x = fmaxf(d * acc.x + dd * sv.x + bb.x, 0.f);
    r.y = fmaxf(d * acc.y + dd * sv.y + bb.y, 0.f);
    r.z = fmaxf(d * acc.z + dd * sv.z + bb.z, 0.f);
    r.w = fmaxf(d * acc.w + dd * sv.w + bb.w, 0.f);
    float4* x4 = (float4*)g_x;
    float4 xo = x4[(size_t)row * 32 + lane];
    xo.x += r.x; xo.y += r.y; xo.z += r.z; xo.w += r.w;
    x4[(size_t)row * 32 + lane] = xo;
}

// ---------------- final LayerNorm -> d_out ----------------------------------
__global__ void ln_k(const float* __restrict__ g, const float* __restrict__ b,
                     float* __restrict__ out) {
    int warp = threadIdx.x >> 5, lane = threadIdx.x & 31;
    int row = blockIdx.x * 8 + warp;
    if (row >= NN) return;
    float4 v = ((const float4*)g_x)[(size_t)row * 32 + lane];
    float s = v.x + v.y + v.z + v.w;
    float s2 = v.x * v.x + v.y * v.y + v.z * v.z + v.w * v.w;
    #pragma unroll
    for (int o = 16; o; o >>= 1) {
        s  += __shfl_xor_sync(0xffffffffu, s, o);
        s2 += __shfl_xor_sync(0xffffffffu, s2, o);
    }
    float mean = s * (1.0f / 128.0f);
    float var = s2 * (1.0f / 128.0f) - mean * mean;
    float rstd = rsqrtf(var + 1e-5f);
    float4 gg = ((const float4*)g)[lane];
    float4 bb = ((const float4*)b)[lane];
    float4 o4;
    o4.x = (v.x - mean) * rstd * gg.x + bb.x;
    o4.y = (v.y - mean) * rstd * gg.y + bb.y;
    o4.z = (v.z - mean) * rstd * gg.z + bb.z;
    o4.w = (v.w - mean) * rstd * gg.w + bb.w;
    ((float4*)out)[(size_t)row * 32 + lane] = o4;
}

// ---------------- launcher --------------------------------------------------
extern "C" void kernel_launch(void* const* d_in, const int* in_sizes, int n_in,
                              void* d_out, int out_size) {
    const float* llm = (const float*)d_in[0];
    const int*   ids = (const int*)d_in[1];
    const int*   ei  = (const int*)d_in[2];
    const float* pW  = (const float*)d_in[3];
    const float* pb  = (const float*)d_in[4];
    const float* emb = (const float*)d_in[5];
    const float* gW  = (const float*)d_in[6];
    const float* gb  = (const float*)d_in[7];
    const float* lg  = (const float*)d_in[8];
    const float* lb  = (const float*)d_in[9];
    const int* src = ei;
    const int* dst = ei + EE;

    const int MB = (NN + 127) / 128;          // 391
    const int WB = (NN + 7) / 8;              // 6250

    // static device symbols -> raw pointers (same address space, no API calls)
    float* d_x  = nullptr; cudaGetSymbolAddress((void**)&d_x,  g_x);
    float* d_xw = nullptr; cudaGetSymbolAddress((void**)&d_xw, g_xw);
    float* d_Wp = nullptr; cudaGetSymbolAddress((void**)&d_Wp, g_Wp);
    float* d_bp = nullptr; cudaGetSymbolAddress((void**)&d_bp, g_bp);

    zero_cnt_k<<<(NN + 255) / 256, 256>>>();
    count_k<<<(EE + 255) / 256, 256>>>(dst);
    scan_k<<<1, 1024>>>();
    fill_k<<<(EE + 255) / 256, 256>>>(src, dst);

    pad_k<<<(LLM * HID + 255) / 256, 256>>>(pW, pb);
    mma_gemm_k<LLM, LLM, true><<<MB, 256>>>(llm, d_Wp, d_bp, d_x);
    struct_k<<<(NN * SD + 255) / 256, 256>>>(ids, emb);

    for (int l = 0; l < 2; l++) {
        mma_gemm_k<HID, HID, false><<<MB, 256>>>(d_x, gW + (size_t)l * HID * HID,
                                                 nullptr, d_xw);
        agg_k<<<WB, 256>>>(gb + (size_t)l * HID);
    }
    ln_k<<<WB, 256>>>(lg, lb, (float*)d_out);
}

// round 7
// speedup vs baseline: 2.2841x; 1.7035x over previous
#include <cuda_runtime.h>

#define NN 50000
#define EE 600000
#define LLM 640
#define HID 128
#define PO 112
#define SD 16

typedef unsigned int uint;

// ---------------- scratch (static device globals; no allocation) ------------
__device__ float g_x[(size_t)NN * HID];
__device__ float g_xw[(size_t)NN * HID];
__device__ float g_dis[NN];
__device__ __align__(16) int g_cnt[NN];
__device__ int   g_rowptr[NN + 1];
__device__ int   g_pos[NN];
__device__ int   g_col[EE];
__device__ float g_Wp[(size_t)LLM * HID];
__device__ float g_bp[HID];

__device__ __forceinline__ uint f2tf32(float x) {
    uint r;
    asm("cvt.rna.tf32.f32 %0, %1;" : "=r"(r) : "f"(x));
    return r;
}

// ---------------- CSR build -------------------------------------------------
__global__ void zero_cnt_k() {
    int i = blockIdx.x * blockDim.x + threadIdx.x;
    if (i < NN) g_cnt[i] = 0;
}

__global__ void count_k(const int* __restrict__ dst) {
    int e = blockIdx.x * blockDim.x + threadIdx.x;
    if (e < EE) atomicAdd(&g_cnt[dst[e]], 1);
}

// Single-block scan, 4 elements/thread (13 rounds). NN % 4 == 0.
__global__ void scan_k() {
    __shared__ int warp_tot[32];
    __shared__ int carry_s;
    int tid = threadIdx.x, lane = tid & 31, w = tid >> 5;
    if (tid == 0) { carry_s = 0; g_rowptr[0] = 0; }
    __syncthreads();
    for (int base = 0; base < NN; base += 4096) {
        int i0 = base + tid * 4;
        int4 v = make_int4(0, 0, 0, 0);
        if (i0 < NN) v = *(const int4*)(g_cnt + i0);
        int s = v.x + v.y + v.z + v.w;
        int x = s;
        #pragma unroll
        for (int o = 1; o < 32; o <<= 1) {
            int y = __shfl_up_sync(0xffffffffu, x, o);
            if (lane >= o) x += y;
        }
        if (lane == 31) warp_tot[w] = x;
        __syncthreads();
        if (w == 0) {
            int t = warp_tot[lane];
            #pragma unroll
            for (int o = 1; o < 32; o <<= 1) {
                int y = __shfl_up_sync(0xffffffffu, t, o);
                if (lane >= o) t += y;
            }
            warp_tot[lane] = t;
        }
        __syncthreads();
        int woff = (w > 0) ? warp_tot[w - 1] : 0;
        int incl = x + woff + carry_s;
        int excl = incl - s;
        if (i0 < NN) {
            int p0 = excl + v.x, p1 = p0 + v.y, p2 = p1 + v.z, p3 = p2 + v.w;
            g_rowptr[i0 + 1] = p0; g_rowptr[i0 + 2] = p1;
            g_rowptr[i0 + 3] = p2; g_rowptr[i0 + 4] = p3;
            g_pos[i0] = excl; g_pos[i0 + 1] = p0; g_pos[i0 + 2] = p1; g_pos[i0 + 3] = p2;
            g_dis[i0 + 0] = rsqrtf(1.0f + (float)v.x);
            g_dis[i0 + 1] = rsqrtf(1.0f + (float)v.y);
            g_dis[i0 + 2] = rsqrtf(1.0f + (float)v.z);
            g_dis[i0 + 3] = rsqrtf(1.0f + (float)v.w);
        }
        __syncthreads();
        if (tid == 1023) carry_s = incl;
        __syncthreads();
    }
}

__global__ void fill_k(const int* __restrict__ src, const int* __restrict__ dst) {
    int e = blockIdx.x * blockDim.x + threadIdx.x;
    if (e < EE) {
        int p = atomicAdd(&g_pos[dst[e]], 1);
        g_col[p] = src[e];
    }
}

// ---------------- pad proj_W [640,112] -> g_Wp [640,128] --------------------
__global__ void pad_k(const float* __restrict__ pW, const float* __restrict__ pb) {
    int i = blockIdx.x * blockDim.x + threadIdx.x;
    if (i < LLM * HID) {
        int r = i >> 7, c = i & 127;
        g_Wp[i] = (c < PO) ? pW[r * PO + c] : 0.0f;
    }
    if (i < HID) g_bp[i] = (i < PO) ? pb[i] : 0.0f;
}

// ---------------- tf32 mma GEMM, double-buffered ----------------------------
// BM=128, BN=128, BK=32. 8 warps (2m x 4n), warp tile 64x32 = 4x4 m16n8k8.
// A blocks (mtile,k8): BSA=132-word stride (staging STS 2-way max).
// B blocks (ntile,k8): BSB=66-word stride  (staging STS 4-way max).
#define BSA 132
#define BSB 66
#define ASZ (32 * BSA)   // 4224 words
#define BSZ (64 * BSB)   // 4224 words

template<int K, int LDA, bool BIAS>
__global__ __launch_bounds__(256, 2) void mma_gemm_k(const float* __restrict__ A,
                                                     const float* __restrict__ W,
                                                     const float* __restrict__ bias,
                                                     float* __restrict__ out) {
    __shared__ __align__(16) uint As[2][ASZ];
    __shared__ __align__(16) uint Bs[2][BSZ];
    int tid = threadIdx.x;
    int lane = tid & 31, wid = tid >> 5;
    int warp_m = wid >> 2;
    int warp_n = wid & 3;
    int row0 = blockIdx.x * 128;
    const int NT = K / 32;

    float acc[4][4][4];
    #pragma unroll
    for (int mt = 0; mt < 4; mt++)
        #pragma unroll
        for (int nt = 0; nt < 4; nt++)
            #pragma unroll
            for (int j = 0; j < 4; j++) acc[mt][nt][j] = 0.0f;

    float4 va[4];

    // ---- helpers inlined via lambdas ----
    auto loadA = [&](int k0) {
        #pragma unroll
        for (int i = 0; i < 4; i++) {
            int f = tid + i * 256;
            int r = f >> 3, c = (f & 7) * 4;
            int gr = row0 + r;
            va[i] = make_float4(0.f, 0.f, 0.f, 0.f);
            if (gr < NN) va[i] = *(const float4*)(A + (size_t)gr * LDA + k0 + c);
        }
    };
    auto storeA = [&](int buf) {
        #pragma unroll
        for (int i = 0; i < 4; i++) {
            int f = tid + i * 256;
            int r = f >> 3, c = (f & 7) * 4;
            int mtile = r >> 4, rloc = r & 15;
            int j = (rloc >> 3) + 2 * ((c >> 2) & 1);
            int tb = (rloc & 7) * 4;
            uint* dst = As[buf] + ((mtile << 2) + (c >> 3)) * BSA + j;
            dst[(tb + 0) * 4] = f2tf32(va[i].x);
            dst[(tb + 1) * 4] = f2tf32(va[i].y);
            dst[(tb + 2) * 4] = f2tf32(va[i].z);
            dst[(tb + 3) * 4] = f2tf32(va[i].w);
        }
    };
    auto stageB = [&](int k0, int buf) {
        #pragma unroll
        for (int i = 0; i < 4; i++) {
            int f = tid + i * 256;
            int kr = f >> 5, c4 = (f & 31) * 4;
            float4 v = *(const float4*)(W + (size_t)(k0 + kr) * 128 + c4);
            int k8 = kr >> 3, kloc = kr & 7;
            int j = kloc >> 2, km = kloc & 3;
            int ntile = c4 >> 3, nb = c4 & 7;
            uint* dst = Bs[buf] + ((ntile << 2) + k8) * BSB + j;
            dst[((nb + 0) * 4 + km) * 2] = f2tf32(v.x);
            dst[((nb + 1) * 4 + km) * 2] = f2tf32(v.y);
            dst[((nb + 2) * 4 + km) * 2] = f2tf32(v.z);
            dst[((nb + 3) * 4 + km) * 2] = f2tf32(v.w);
        }
    };

    // ---- prologue ----
    loadA(0);
    storeA(0);
    stageB(0, 0);
    __syncthreads();

    for (int it = 0; it < NT; it++) {
        int cur = it & 1;
        if (it + 1 < NT) loadA((it + 1) * 32);   // LDG in flight during mma

        #pragma unroll
        for (int k8 = 0; k8 < 4; k8++) {
            uint4 a[4];
            uint2 b[4];
            #pragma unroll
            for (int mt = 0; mt < 4; mt++)
                a[mt] = *(const uint4*)(As[cur] + (((warp_m * 4 + mt) << 2) + k8) * BSA + lane * 4);
            #pragma unroll
            for (int nt = 0; nt < 4; nt++)
                b[nt] = *(const uint2*)(Bs[cur] + (((warp_n * 4 + nt) << 2) + k8) * BSB + lane * 2);
            #pragma unroll
            for (int mt = 0; mt < 4; mt++)
                #pragma unroll
                for (int nt = 0; nt < 4; nt++) {
                    asm volatile(
                        "mma.sync.aligned.m16n8k8.row.col.f32.tf32.tf32.f32 "
                        "{%0,%1,%2,%3}, {%4,%5,%6,%7}, {%8,%9}, {%0,%1,%2,%3};"
                        : "+f"(acc[mt][nt][0]), "+f"(acc[mt][nt][1]),
                          "+f"(acc[mt][nt][2]), "+f"(acc[mt][nt][3])
                        : "r"(a[mt].x), "r"(a[mt].y), "r"(a[mt].z), "r"(a[mt].w),
                          "r"(b[nt].x), "r"(b[nt].y));
                }
        }

        if (it + 1 < NT) {
            __syncthreads();               // all warps done reading buf cur^1's prior contents
            storeA(cur ^ 1);
            stageB((it + 1) * 32, cur ^ 1);
            __syncthreads();
        }
    }

    // ---- epilogue ----
    #pragma unroll
    for (int mt = 0; mt < 4; mt++) {
        int gr0 = row0 + warp_m * 64 + mt * 16 + (lane >> 2);
        #pragma unroll
        for (int nt = 0; nt < 4; nt++) {
            int col = warp_n * 32 + nt * 8 + (lane & 3) * 2;
            float b0 = 0.f, b1 = 0.f;
            if (BIAS) { b0 = bias[col]; b1 = bias[col + 1]; }
            if (gr0 < NN)
                *(float2*)(out + (size_t)gr0 * 128 + col) =
                    make_float2(acc[mt][nt][0] + b0, acc[mt][nt][1] + b1);
            if (gr0 + 8 < NN)
                *(float2*)(out + (size_t)(gr0 + 8) * 128 + col) =
                    make_float2(acc[mt][nt][2] + b0, acc[mt][nt][3] + b1);
        }
    }
}

// ---------------- struct embedding concat: g_x[:, 112:128] -----------------
__global__ void struct_k(const int* __restrict__ ids, const float* __restrict__ emb) {
    int idx = blockIdx.x * blockDim.x + threadIdx.x;
    if (idx < NN * SD) {
        int i = idx >> 4, t = idx & 15;
        g_x[(size_t)i * HID + PO + t] = emb[ids[i] * SD + t];
    }
}

// ---------------- aggregation + self-loop + bias + relu + residual ----------
__global__ void agg_k(const float* __restrict__ bias) {
    int warp = threadIdx.x >> 5, lane = threadIdx.x & 31;
    int row = blockIdx.x * 8 + warp;
    if (row >= NN) return;
    const float4* xw4 = (const float4*)g_xw;
    float4 acc = make_float4(0.f, 0.f, 0.f, 0.f);
    int e = g_rowptr[row], end = g_rowptr[row + 1];
    for (; e < end; e++) {
        int s = g_col[e];
        float w = g_dis[s];
        float4 v = xw4[(size_t)s * 32 + lane];
        acc.x += w * v.x; acc.y += w * v.y; acc.z += w * v.z; acc.w += w * v.w;
    }
    float d = g_dis[row];
    float dd = d * d;
    float4 sv = xw4[(size_t)row * 32 + lane];
    float4 bb = ((const float4*)bias)[lane];
    float4 r;
    r.x = fmaxf(d * acc.x + dd * sv.x + bb.x, 0.f);
    r.y = fmaxf(d * acc.y + dd * sv.y + bb.y, 0.f);
    r.z = fmaxf(d * acc.z + dd * sv.z + bb.z, 0.f);
    r.w = fmaxf(d * acc.w + dd * sv.w + bb.w, 0.f);
    float4* x4 = (float4*)g_x;
    float4 xo = x4[(size_t)row * 32 + lane];
    xo.x += r.x; xo.y += r.y; xo.z += r.z; xo.w += r.w;
    x4[(size_t)row * 32 + lane] = xo;
}

// ---------------- final LayerNorm -> d_out ----------------------------------
__global__ void ln_k(const float* __restrict__ g, const float* __restrict__ b,
                     float* __restrict__ out) {
    int warp = threadIdx.x >> 5, lane = threadIdx.x & 31;
    int row = blockIdx.x * 8 + warp;
    if (row >= NN) return;
    float4 v = ((const float4*)g_x)[(size_t)row * 32 + lane];
    float s = v.x + v.y + v.z + v.w;
    float s2 = v.x * v.x + v.y * v.y + v.z * v.z + v.w * v.w;
    #pragma unroll
    for (int o = 16; o; o >>= 1) {
        s  += __shfl_xor_sync(0xffffffffu, s, o);
        s2 += __shfl_xor_sync(0xffffffffu, s2, o);
    }
    float mean = s * (1.0f / 128.0f);
    float var = s2 * (1.0f / 128.0f) - mean * mean;
    float rstd = rsqrtf(var + 1e-5f);
    float4 gg = ((const float4*)g)[lane];
    float4 bb = ((const float4*)b)[lane];
    float4 o4;
    o4.x = (v.x - mean) * rstd * gg.x + bb.x;
    o4.y = (v.y - mean) * rstd * gg.y + bb.y;
    o4.z = (v.z - mean) * rstd * gg.z + bb.z;
    o4.w = (v.w - mean) * rstd * gg.w + bb.w;
    ((float4*)out)[(size_t)row * 32 + lane] = o4;
}

// ---------------- launcher --------------------------------------------------
extern "C" void kernel_launch(void* const* d_in, const int* in_sizes, int n_in,
                              void* d_out, int out_size) {
    const float* llm = (const float*)d_in[0];
    const int*   ids = (const int*)d_in[1];
    const int*   ei  = (const int*)d_in[2];
    const float* pW  = (const float*)d_in[3];
    const float* pb  = (const float*)d_in[4];
    const float* emb = (const float*)d_in[5];
    const float* gW  = (const float*)d_in[6];
    const float* gb  = (const float*)d_in[7];
    const float* lg  = (const float*)d_in[8];
    const float* lb  = (const float*)d_in[9];
    const int* src = ei;
    const int* dst = ei + EE;

    const int MB = (NN + 127) / 128;
    const int WB = (NN + 7) / 8;

    float* d_x  = nullptr; cudaGetSymbolAddress((void**)&d_x,  g_x);
    float* d_xw = nullptr; cudaGetSymbolAddress((void**)&d_xw, g_xw);
    float* d_Wp = nullptr; cudaGetSymbolAddress((void**)&d_Wp, g_Wp);
    float* d_bp = nullptr; cudaGetSymbolAddress((void**)&d_bp, g_bp);

    zero_cnt_k<<<(NN + 255) / 256, 256>>>();
    count_k<<<(EE + 255) / 256, 256>>>(dst);
    scan_k<<<1, 1024>>>();
    fill_k<<<(EE + 255) / 256, 256>>>(src, dst);

    pad_k<<<(LLM * HID + 255) / 256, 256>>>(pW, pb);
    mma_gemm_k<LLM, LLM, true><<<MB, 256>>>(llm, d_Wp, d_bp, d_x);
    struct_k<<<(NN * SD + 255) / 256, 256>>>(ids, emb);

    for (int l = 0; l < 2; l++) {
        mma_gemm_k<HID, HID, false><<<MB, 256>>>(d_x, gW + (size_t)l * HID * HID,
                                                 nullptr, d_xw);
        agg_k<<<WB, 256>>>(gb + (size_t)l * HID);
    }
    ln_k<<<WB, 256>>>(lg, lb, (float*)d_out);
}

// round 8
// speedup vs baseline: 2.3008x; 1.0073x over previous
#include <cuda_runtime.h>

#define NN 50000
#define EE 600000
#define LLM 640
#define HID 128
#define PO 112
#define SD 16

typedef unsigned int uint;

// ---------------- scratch (static device globals; no allocation) ------------
__device__ float g_x[(size_t)NN * HID];
__device__ float g_xw[(size_t)NN * HID];     // holds xws = dis * (x@W)
__device__ float g_dis[NN];
__device__ __align__(16) int g_cnt[NN];
__device__ int   g_rowptr[NN + 1];
__device__ int   g_pos[NN];
__device__ __align__(16) int g_col[EE];
__device__ float g_Wp[(size_t)LLM * HID];
__device__ float g_bp[HID];

__device__ __forceinline__ uint f2tf32(float x) {
    uint r;
    asm("cvt.rna.tf32.f32 %0, %1;" : "=r"(r) : "f"(x));
    return r;
}

// ---------------- pad proj_W + zero counters --------------------------------
__global__ void pad_k(const float* __restrict__ pW, const float* __restrict__ pb) {
    int i = blockIdx.x * blockDim.x + threadIdx.x;
    if (i < LLM * HID) {
        int r = i >> 7, c = i & 127;
        g_Wp[i] = (c < PO) ? pW[r * PO + c] : 0.0f;
    }
    if (i < HID) g_bp[i] = (i < PO) ? pb[i] : 0.0f;
    if (i < NN) g_cnt[i] = 0;
}

// ---------------- CSR build -------------------------------------------------
__global__ void count_k(const int* __restrict__ dst) {
    int e0 = (blockIdx.x * blockDim.x + threadIdx.x) * 4;
    if (e0 < EE) {
        int4 d = *(const int4*)(dst + e0);
        atomicAdd(&g_cnt[d.x], 1);
        atomicAdd(&g_cnt[d.y], 1);
        atomicAdd(&g_cnt[d.z], 1);
        atomicAdd(&g_cnt[d.w], 1);
    }
}

// Single-block scan, 4 elements/thread. NN % 4 == 0.
__global__ void scan_k() {
    __shared__ int warp_tot[32];
    __shared__ int carry_s;
    int tid = threadIdx.x, lane = tid & 31, w = tid >> 5;
    if (tid == 0) { carry_s = 0; g_rowptr[0] = 0; }
    __syncthreads();
    for (int base = 0; base < NN; base += 4096) {
        int i0 = base + tid * 4;
        int4 v = make_int4(0, 0, 0, 0);
        if (i0 < NN) v = *(const int4*)(g_cnt + i0);
        int s = v.x + v.y + v.z + v.w;
        int x = s;
        #pragma unroll
        for (int o = 1; o < 32; o <<= 1) {
            int y = __shfl_up_sync(0xffffffffu, x, o);
            if (lane >= o) x += y;
        }
        if (lane == 31) warp_tot[w] = x;
        __syncthreads();
        if (w == 0) {
            int t = warp_tot[lane];
            #pragma unroll
            for (int o = 1; o < 32; o <<= 1) {
                int y = __shfl_up_sync(0xffffffffu, t, o);
                if (lane >= o) t += y;
            }
            warp_tot[lane] = t;
        }
        __syncthreads();
        int woff = (w > 0) ? warp_tot[w - 1] : 0;
        int incl = x + woff + carry_s;
        int excl = incl - s;
        if (i0 < NN) {
            int p0 = excl + v.x, p1 = p0 + v.y, p2 = p1 + v.z, p3 = p2 + v.w;
            g_rowptr[i0 + 1] = p0; g_rowptr[i0 + 2] = p1;
            g_rowptr[i0 + 3] = p2; g_rowptr[i0 + 4] = p3;
            g_pos[i0] = excl; g_pos[i0 + 1] = p0; g_pos[i0 + 2] = p1; g_pos[i0 + 3] = p2;
            g_dis[i0 + 0] = rsqrtf(1.0f + (float)v.x);
            g_dis[i0 + 1] = rsqrtf(1.0f + (float)v.y);
            g_dis[i0 + 2] = rsqrtf(1.0f + (float)v.z);
            g_dis[i0 + 3] = rsqrtf(1.0f + (float)v.w);
        }
        __syncthreads();
        if (tid == 1023) carry_s = incl;
        __syncthreads();
    }
}

__global__ void fill_k(const int* __restrict__ src, const int* __restrict__ dst) {
    int e0 = (blockIdx.x * blockDim.x + threadIdx.x) * 4;
    if (e0 < EE) {
        int4 d = *(const int4*)(dst + e0);
        int4 s = *(const int4*)(src + e0);
        int p0 = atomicAdd(&g_pos[d.x], 1);
        int p1 = atomicAdd(&g_pos[d.y], 1);
        int p2 = atomicAdd(&g_pos[d.z], 1);
        int p3 = atomicAdd(&g_pos[d.w], 1);
        g_col[p0] = s.x; g_col[p1] = s.y; g_col[p2] = s.z; g_col[p3] = s.w;
    }
}

// ---------------- tf32 mma GEMM, double-buffered ----------------------------
// BM=128, BN=128, BK=32. 8 warps (2m x 4n), warp tile 64x32 = 4x4 m16n8k8.
// SCALE: multiply output rows by g_dis[row] (produces xws for aggregation).
#define BSA 132
#define BSB 66
#define ASZ (32 * BSA)
#define BSZ (64 * BSB)

template<int K, int LDA, bool BIAS, bool SCALE>
__global__ __launch_bounds__(256, 2) void mma_gemm_k(const float* __restrict__ A,
                                                     const float* __restrict__ W,
                                                     const float* __restrict__ bias,
                                                     float* __restrict__ out) {
    __shared__ __align__(16) uint As[2][ASZ];
    __shared__ __align__(16) uint Bs[2][BSZ];
    int tid = threadIdx.x;
    int lane = tid & 31, wid = tid >> 5;
    int warp_m = wid >> 2;
    int warp_n = wid & 3;
    int row0 = blockIdx.x * 128;
    const int NT = K / 32;

    float acc[4][4][4];
    #pragma unroll
    for (int mt = 0; mt < 4; mt++)
        #pragma unroll
        for (int nt = 0; nt < 4; nt++)
            #pragma unroll
            for (int j = 0; j < 4; j++) acc[mt][nt][j] = 0.0f;

    float4 va[4];

    auto loadA = [&](int k0) {
        #pragma unroll
        for (int i = 0; i < 4; i++) {
            int f = tid + i * 256;
            int r = f >> 3, c = (f & 7) * 4;
            int gr = row0 + r;
            va[i] = make_float4(0.f, 0.f, 0.f, 0.f);
            if (gr < NN) va[i] = *(const float4*)(A + (size_t)gr * LDA + k0 + c);
        }
    };
    auto storeA = [&](int buf) {
        #pragma unroll
        for (int i = 0; i < 4; i++) {
            int f = tid + i * 256;
            int r = f >> 3, c = (f & 7) * 4;
            int mtile = r >> 4, rloc = r & 15;
            int j = (rloc >> 3) + 2 * ((c >> 2) & 1);
            int tb = (rloc & 7) * 4;
            uint* dst = As[buf] + ((mtile << 2) + (c >> 3)) * BSA + j;
            dst[(tb + 0) * 4] = f2tf32(va[i].x);
            dst[(tb + 1) * 4] = f2tf32(va[i].y);
            dst[(tb + 2) * 4] = f2tf32(va[i].z);
            dst[(tb + 3) * 4] = f2tf32(va[i].w);
        }
    };
    auto stageB = [&](int k0, int buf) {
        #pragma unroll
        for (int i = 0; i < 4; i++) {
            int f = tid + i * 256;
            int kr = f >> 5, c4 = (f & 31) * 4;
            float4 v = *(const float4*)(W + (size_t)(k0 + kr) * 128 + c4);
            int k8 = kr >> 3, kloc = kr & 7;
            int j = kloc >> 2, km = kloc & 3;
            int ntile = c4 >> 3, nb = c4 & 7;
            uint* dst = Bs[buf] + ((ntile << 2) + k8) * BSB + j;
            dst[((nb + 0) * 4 + km) * 2] = f2tf32(v.x);
            dst[((nb + 1) * 4 + km) * 2] = f2tf32(v.y);
            dst[((nb + 2) * 4 + km) * 2] = f2tf32(v.z);
            dst[((nb + 3) * 4 + km) * 2] = f2tf32(v.w);
        }
    };

    loadA(0);
    storeA(0);
    stageB(0, 0);
    __syncthreads();

    for (int it = 0; it < NT; it++) {
        int cur = it & 1;
        if (it + 1 < NT) loadA((it + 1) * 32);

        #pragma unroll
        for (int k8 = 0; k8 < 4; k8++) {
            uint4 a[4];
            uint2 b[4];
            #pragma unroll
            for (int mt = 0; mt < 4; mt++)
                a[mt] = *(const uint4*)(As[cur] + (((warp_m * 4 + mt) << 2) + k8) * BSA + lane * 4);
            #pragma unroll
            for (int nt = 0; nt < 4; nt++)
                b[nt] = *(const uint2*)(Bs[cur] + (((warp_n * 4 + nt) << 2) + k8) * BSB + lane * 2);
            #pragma unroll
            for (int mt = 0; mt < 4; mt++)
                #pragma unroll
                for (int nt = 0; nt < 4; nt++) {
                    asm volatile(
                        "mma.sync.aligned.m16n8k8.row.col.f32.tf32.tf32.f32 "
                        "{%0,%1,%2,%3}, {%4,%5,%6,%7}, {%8,%9}, {%0,%1,%2,%3};"
                        : "+f"(acc[mt][nt][0]), "+f"(acc[mt][nt][1]),
                          "+f"(acc[mt][nt][2]), "+f"(acc[mt][nt][3])
                        : "r"(a[mt].x), "r"(a[mt].y), "r"(a[mt].z), "r"(a[mt].w),
                          "r"(b[nt].x), "r"(b[nt].y));
                }
        }

        if (it + 1 < NT) {
            __syncthreads();
            storeA(cur ^ 1);
            stageB((it + 1) * 32, cur ^ 1);
            __syncthreads();
        }
    }

    // ---- epilogue ----
    #pragma unroll
    for (int mt = 0; mt < 4; mt++) {
        int gr0 = row0 + warp_m * 64 + mt * 16 + (lane >> 2);
        float s0 = 1.f, s1 = 1.f;
        if (SCALE) {
            if (gr0 < NN) s0 = g_dis[gr0];
            if (gr0 + 8 < NN) s1 = g_dis[gr0 + 8];
        }
        #pragma unroll
        for (int nt = 0; nt < 4; nt++) {
            int col = warp_n * 32 + nt * 8 + (lane & 3) * 2;
            float b0 = 0.f, b1 = 0.f;
            if (BIAS) { b0 = bias[col]; b1 = bias[col + 1]; }
            if (gr0 < NN)
                *(float2*)(out + (size_t)gr0 * 128 + col) =
                    make_float2(acc[mt][nt][0] * s0 + b0, acc[mt][nt][1] * s0 + b1);
            if (gr0 + 8 < NN)
                *(float2*)(out + (size_t)(gr0 + 8) * 128 + col) =
                    make_float2(acc[mt][nt][2] * s1 + b0, acc[mt][nt][3] * s1 + b1);
        }
    }
}

// ---------------- struct embedding concat: g_x[:, 112:128] -----------------
__global__ void struct_k(const int* __restrict__ ids, const float* __restrict__ emb) {
    int idx = blockIdx.x * blockDim.x + threadIdx.x;
    if (idx < NN * SD) {
        int i = idx >> 4, t = idx & 15;
        g_x[(size_t)i * HID + PO + t] = emb[ids[i] * SD + t];
    }
}

// ---------------- aggregation (xws pre-scaled) + relu + residual ------------
// agg = d_dst * (sum_src xws[src] + xws[dst]) + b ; x += relu(agg)
// LAST: fuse LayerNorm and write to out instead of g_x.
template<bool LAST>
__global__ void agg_k(const float* __restrict__ bias,
                      const float* __restrict__ lng,
                      const float* __restrict__ lnb,
                      float* __restrict__ out) {
    int warp = threadIdx.x >> 5, lane = threadIdx.x & 31;
    int row = blockIdx.x * 8 + warp;
    if (row >= NN) return;
    const float4* xw4 = (const float4*)g_xw;
    float4 acc = xw4[(size_t)row * 32 + lane];       // self term (xws[dst])
    int e = g_rowptr[row], end = g_rowptr[row + 1];
    // 4-way unrolled gather: batch col loads, then 4 independent float4 loads
    for (; e + 4 <= end; e += 4) {
        int s0 = g_col[e], s1 = g_col[e + 1], s2 = g_col[e + 2], s3 = g_col[e + 3];
        float4 v0 = xw4[(size_t)s0 * 32 + lane];
        float4 v1 = xw4[(size_t)s1 * 32 + lane];
        float4 v2 = xw4[(size_t)s2 * 32 + lane];
        float4 v3 = xw4[(size_t)s3 * 32 + lane];
        acc.x += (v0.x + v1.x) + (v2.x + v3.x);
        acc.y += (v0.y + v1.y) + (v2.y + v3.y);
        acc.z += (v0.z + v1.z) + (v2.z + v3.z);
        acc.w += (v0.w + v1.w) + (v2.w + v3.w);
    }
    for (; e < end; e++) {
        int s = g_col[e];
        float4 v = xw4[(size_t)s * 32 + lane];
        acc.x += v.x; acc.y += v.y; acc.z += v.z; acc.w += v.w;
    }
    float d = g_dis[row];
    float4 bb = ((const float4*)bias)[lane];
    float4 xo = ((const float4*)g_x)[(size_t)row * 32 + lane];
    float4 v;
    v.x = xo.x + fmaxf(d * acc.x + bb.x, 0.f);
    v.y = xo.y + fmaxf(d * acc.y + bb.y, 0.f);
    v.z = xo.z + fmaxf(d * acc.z + bb.z, 0.f);
    v.w = xo.w + fmaxf(d * acc.w + bb.w, 0.f);
    if (!LAST) {
        ((float4*)g_x)[(size_t)row * 32 + lane] = v;
    } else {
        float s = v.x + v.y + v.z + v.w;
        float s2 = v.x * v.x + v.y * v.y + v.z * v.z + v.w * v.w;
        #pragma unroll
        for (int o = 16; o; o >>= 1) {
            s  += __shfl_xor_sync(0xffffffffu, s, o);
            s2 += __shfl_xor_sync(0xffffffffu, s2, o);
        }
        float mean = s * (1.0f / 128.0f);
        float var = s2 * (1.0f / 128.0f) - mean * mean;
        float rstd = rsqrtf(var + 1e-5f);
        float4 gg = ((const float4*)lng)[lane];
        float4 lbb = ((const float4*)lnb)[lane];
        float4 o4;
        o4.x = (v.x - mean) * rstd * gg.x + lbb.x;
        o4.y = (v.y - mean) * rstd * gg.y + lbb.y;
        o4.z = (v.z - mean) * rstd * gg.z + lbb.z;
        o4.w = (v.w - mean) * rstd * gg.w + lbb.w;
        ((float4*)out)[(size_t)row * 32 + lane] = o4;
    }
}

// ---------------- launcher --------------------------------------------------
extern "C" void kernel_launch(void* const* d_in, const int* in_sizes, int n_in,
                              void* d_out, int out_size) {
    const float* llm = (const float*)d_in[0];
    const int*   ids = (const int*)d_in[1];
    const int*   ei  = (const int*)d_in[2];
    const float* pW  = (const float*)d_in[3];
    const float* pb  = (const float*)d_in[4];
    const float* emb = (const float*)d_in[5];
    const float* gW  = (const float*)d_in[6];
    const float* gb  = (const float*)d_in[7];
    const float* lg  = (const float*)d_in[8];
    const float* lb  = (const float*)d_in[9];
    const int* src = ei;
    const int* dst = ei + EE;

    const int MB = (NN + 127) / 128;
    const int WB = (NN + 7) / 8;
    const int EB4 = (EE / 4 + 255) / 256;

    float* d_x  = nullptr; cudaGetSymbolAddress((void**)&d_x,  g_x);
    float* d_xw = nullptr; cudaGetSymbolAddress((void**)&d_xw, g_xw);
    float* d_Wp = nullptr; cudaGetSymbolAddress((void**)&d_Wp, g_Wp);
    float* d_bp = nullptr; cudaGetSymbolAddress((void**)&d_bp, g_bp);

    pad_k<<<(LLM * HID + 255) / 256, 256>>>(pW, pb);      // also zeroes g_cnt
    count_k<<<EB4, 256>>>(dst);
    scan_k<<<1, 1024>>>();
    fill_k<<<EB4, 256>>>(src, dst);

    mma_gemm_k<LLM, LLM, true, false><<<MB, 256>>>(llm, d_Wp, d_bp, d_x);
    struct_k<<<(NN * SD + 255) / 256, 256>>>(ids, emb);

    for (int l = 0; l < 2; l++) {
        mma_gemm_k<HID, HID, false, true><<<MB, 256>>>(d_x, gW + (size_t)l * HID * HID,
                                                       nullptr, d_xw);
        if (l == 0)
            agg_k<false><<<WB, 256>>>(gb, nullptr, nullptr, nullptr);
        else
            agg_k<true><<<WB, 256>>>(gb + HID, lg, lb, (float*)d_out);
    }
}

// round 9
// speedup vs baseline: 2.8738x; 1.2491x over previous
#include <cuda_runtime.h>
#include <cuda_fp16.h>

#define NN 50000
#define EE 600000
#define LLM 640
#define HID 128
#define PO 112
#define SD 16

typedef unsigned int uint;

// ---------------- scratch (static device globals; no allocation) ------------
__device__ float  g_x[(size_t)NN * HID];
__device__ __half g_xwh[(size_t)NN * HID];   // xws = dis * (x@W), fp16
__device__ float  g_dis[NN];
__device__ __align__(16) int g_cnt[NN];
__device__ int    g_rowptr[NN + 1];
__device__ int    g_pos[NN];
__device__ __align__(16) int g_col[EE];
__device__ float  g_Wp[(size_t)LLM * HID];
__device__ float  g_bp[HID];

__device__ __forceinline__ uint f2tf32(float x) {
    uint r;
    asm("cvt.rna.tf32.f32 %0, %1;" : "=r"(r) : "f"(x));
    return r;
}
__device__ __forceinline__ float4 h8_to_f4(uint2 p) {
    __half2 a = *(__half2*)&p.x, b = *(__half2*)&p.y;
    float2 fa = __half22float2(a), fb = __half22float2(b);
    return make_float4(fa.x, fa.y, fb.x, fb.y);
}

// ---------------- pad proj_W + zero counters --------------------------------
__global__ void pad_k(const float* __restrict__ pW, const float* __restrict__ pb) {
    int i = blockIdx.x * blockDim.x + threadIdx.x;
    if (i < LLM * HID) {
        int r = i >> 7, c = i & 127;
        g_Wp[i] = (c < PO) ? pW[r * PO + c] : 0.0f;
    }
    if (i < HID) g_bp[i] = (i < PO) ? pb[i] : 0.0f;
    if (i < NN) g_cnt[i] = 0;
}

// ---------------- CSR build (runs on side stream) ---------------------------
__global__ void count_k(const int* __restrict__ dst) {
    int e0 = (blockIdx.x * blockDim.x + threadIdx.x) * 4;
    if (e0 < EE) {
        int4 d = *(const int4*)(dst + e0);
        atomicAdd(&g_cnt[d.x], 1);
        atomicAdd(&g_cnt[d.y], 1);
        atomicAdd(&g_cnt[d.z], 1);
        atomicAdd(&g_cnt[d.w], 1);
    }
}

__global__ void scan_k() {
    __shared__ int warp_tot[32];
    __shared__ int carry_s;
    int tid = threadIdx.x, lane = tid & 31, w = tid >> 5;
    if (tid == 0) { carry_s = 0; g_rowptr[0] = 0; }
    __syncthreads();
    for (int base = 0; base < NN; base += 4096) {
        int i0 = base + tid * 4;
        int4 v = make_int4(0, 0, 0, 0);
        if (i0 < NN) v = *(const int4*)(g_cnt + i0);
        int s = v.x + v.y + v.z + v.w;
        int x = s;
        #pragma unroll
        for (int o = 1; o < 32; o <<= 1) {
            int y = __shfl_up_sync(0xffffffffu, x, o);
            if (lane >= o) x += y;
        }
        if (lane == 31) warp_tot[w] = x;
        __syncthreads();
        if (w == 0) {
            int t = warp_tot[lane];
            #pragma unroll
            for (int o = 1; o < 32; o <<= 1) {
                int y = __shfl_up_sync(0xffffffffu, t, o);
                if (lane >= o) t += y;
            }
            warp_tot[lane] = t;
        }
        __syncthreads();
        int woff = (w > 0) ? warp_tot[w - 1] : 0;
        int incl = x + woff + carry_s;
        int excl = incl - s;
        if (i0 < NN) {
            int p0 = excl + v.x, p1 = p0 + v.y, p2 = p1 + v.z, p3 = p2 + v.w;
            g_rowptr[i0 + 1] = p0; g_rowptr[i0 + 2] = p1;
            g_rowptr[i0 + 3] = p2; g_rowptr[i0 + 4] = p3;
            g_pos[i0] = excl; g_pos[i0 + 1] = p0; g_pos[i0 + 2] = p1; g_pos[i0 + 3] = p2;
            g_dis[i0 + 0] = rsqrtf(1.0f + (float)v.x);
            g_dis[i0 + 1] = rsqrtf(1.0f + (float)v.y);
            g_dis[i0 + 2] = rsqrtf(1.0f + (float)v.z);
            g_dis[i0 + 3] = rsqrtf(1.0f + (float)v.w);
        }
        __syncthreads();
        if (tid == 1023) carry_s = incl;
        __syncthreads();
    }
}

__global__ void fill_k(const int* __restrict__ src, const int* __restrict__ dst) {
    int e0 = (blockIdx.x * blockDim.x + threadIdx.x) * 4;
    if (e0 < EE) {
        int4 d = *(const int4*)(dst + e0);
        int4 s = *(const int4*)(src + e0);
        int p0 = atomicAdd(&g_pos[d.x], 1);
        int p1 = atomicAdd(&g_pos[d.y], 1);
        int p2 = atomicAdd(&g_pos[d.z], 1);
        int p3 = atomicAdd(&g_pos[d.w], 1);
        g_col[p0] = s.x; g_col[p1] = s.y; g_col[p2] = s.z; g_col[p3] = s.w;
    }
}

// ---------------- tf32 mma GEMM, double-buffered ----------------------------
// BM=128, BN=128, BK=32. 8 warps (2m x 4n), warp tile 64x32 = 4x4 m16n8k8.
// PROJ: fp32 out = acc + bias for cols<112, emb[ids] for cols>=112.
// !PROJ: fp16 out = dis[row] * acc  (xws for aggregation).
#define BSA 132
#define BSB 66
#define ASZ (32 * BSA)
#define BSZ (64 * BSB)

template<int K, int LDA, bool PROJ>
__global__ __launch_bounds__(256, 2) void mma_gemm_k(const float* __restrict__ A,
                                                     const float* __restrict__ W,
                                                     const float* __restrict__ bias,
                                                     const int* __restrict__ ids,
                                                     const float* __restrict__ emb,
                                                     float* __restrict__ outf,
                                                     __half* __restrict__ outh) {
    __shared__ __align__(16) uint As[2][ASZ];
    __shared__ __align__(16) uint Bs[2][BSZ];
    int tid = threadIdx.x;
    int lane = tid & 31, wid = tid >> 5;
    int warp_m = wid >> 2;
    int warp_n = wid & 3;
    int row0 = blockIdx.x * 128;
    const int NT = K / 32;

    float acc[4][4][4];
    #pragma unroll
    for (int mt = 0; mt < 4; mt++)
        #pragma unroll
        for (int nt = 0; nt < 4; nt++)
            #pragma unroll
            for (int j = 0; j < 4; j++) acc[mt][nt][j] = 0.0f;

    float4 va[4];

    auto loadA = [&](int k0) {
        #pragma unroll
        for (int i = 0; i < 4; i++) {
            int f = tid + i * 256;
            int r = f >> 3, c = (f & 7) * 4;
            int gr = row0 + r;
            va[i] = make_float4(0.f, 0.f, 0.f, 0.f);
            if (gr < NN) va[i] = *(const float4*)(A + (size_t)gr * LDA + k0 + c);
        }
    };
    auto storeA = [&](int buf) {
        #pragma unroll
        for (int i = 0; i < 4; i++) {
            int f = tid + i * 256;
            int r = f >> 3, c = (f & 7) * 4;
            int mtile = r >> 4, rloc = r & 15;
            int j = (rloc >> 3) + 2 * ((c >> 2) & 1);
            int tb = (rloc & 7) * 4;
            uint* dst = As[buf] + ((mtile << 2) + (c >> 3)) * BSA + j;
            dst[(tb + 0) * 4] = f2tf32(va[i].x);
            dst[(tb + 1) * 4] = f2tf32(va[i].y);
            dst[(tb + 2) * 4] = f2tf32(va[i].z);
            dst[(tb + 3) * 4] = f2tf32(va[i].w);
        }
    };
    auto stageB = [&](int k0, int buf) {
        #pragma unroll
        for (int i = 0; i < 4; i++) {
            int f = tid + i * 256;
            int kr = f >> 5, c4 = (f & 31) * 4;
            float4 v = *(const float4*)(W + (size_t)(k0 + kr) * 128 + c4);
            int k8 = kr >> 3, kloc = kr & 7;
            int j = kloc >> 2, km = kloc & 3;
            int ntile = c4 >> 3, nb = c4 & 7;
            uint* dst = Bs[buf] + ((ntile << 2) + k8) * BSB + j;
            dst[((nb + 0) * 4 + km) * 2] = f2tf32(v.x);
            dst[((nb + 1) * 4 + km) * 2] = f2tf32(v.y);
            dst[((nb + 2) * 4 + km) * 2] = f2tf32(v.z);
            dst[((nb + 3) * 4 + km) * 2] = f2tf32(v.w);
        }
    };

    loadA(0);
    storeA(0);
    stageB(0, 0);
    __syncthreads();

    for (int it = 0; it < NT; it++) {
        int cur = it & 1;
        if (it + 1 < NT) loadA((it + 1) * 32);

        #pragma unroll
        for (int k8 = 0; k8 < 4; k8++) {
            uint4 a[4];
            uint2 b[4];
            #pragma unroll
            for (int mt = 0; mt < 4; mt++)
                a[mt] = *(const uint4*)(As[cur] + (((warp_m * 4 + mt) << 2) + k8) * BSA + lane * 4);
            #pragma unroll
            for (int nt = 0; nt < 4; nt++)
                b[nt] = *(const uint2*)(Bs[cur] + (((warp_n * 4 + nt) << 2) + k8) * BSB + lane * 2);
            #pragma unroll
            for (int mt = 0; mt < 4; mt++)
                #pragma unroll
                for (int nt = 0; nt < 4; nt++) {
                    asm volatile(
                        "mma.sync.aligned.m16n8k8.row.col.f32.tf32.tf32.f32 "
                        "{%0,%1,%2,%3}, {%4,%5,%6,%7}, {%8,%9}, {%0,%1,%2,%3};"
                        : "+f"(acc[mt][nt][0]), "+f"(acc[mt][nt][1]),
                          "+f"(acc[mt][nt][2]), "+f"(acc[mt][nt][3])
                        : "r"(a[mt].x), "r"(a[mt].y), "r"(a[mt].z), "r"(a[mt].w),
                          "r"(b[nt].x), "r"(b[nt].y));
                }
        }

        if (it + 1 < NT) {
            __syncthreads();
            storeA(cur ^ 1);
            stageB((it + 1) * 32, cur ^ 1);
            __syncthreads();
        }
    }

    // ---- epilogue ----
    #pragma unroll
    for (int mt = 0; mt < 4; mt++) {
        int gr0 = row0 + warp_m * 64 + mt * 16 + (lane >> 2);
        int gr1 = gr0 + 8;
        float s0 = 1.f, s1 = 1.f;
        if (!PROJ) {
            if (gr0 < NN) s0 = g_dis[gr0];
            if (gr1 < NN) s1 = g_dis[gr1];
        }
        #pragma unroll
        for (int nt = 0; nt < 4; nt++) {
            int col = warp_n * 32 + nt * 8 + (lane & 3) * 2;
            if (PROJ) {
                if (col < PO) {
                    float b0 = bias[col], b1 = bias[col + 1];
                    if (gr0 < NN)
                        *(float2*)(outf + (size_t)gr0 * 128 + col) =
                            make_float2(acc[mt][nt][0] + b0, acc[mt][nt][1] + b1);
                    if (gr1 < NN)
                        *(float2*)(outf + (size_t)gr1 * 128 + col) =
                            make_float2(acc[mt][nt][2] + b0, acc[mt][nt][3] + b1);
                } else {
                    // struct embedding fold: exact fp32 from emb[ids[row]]
                    int t = col - PO;
                    if (gr0 < NN) {
                        float2 ev = *(const float2*)(emb + ids[gr0] * SD + t);
                        *(float2*)(outf + (size_t)gr0 * 128 + col) = ev;
                    }
                    if (gr1 < NN) {
                        float2 ev = *(const float2*)(emb + ids[gr1] * SD + t);
                        *(float2*)(outf + (size_t)gr1 * 128 + col) = ev;
                    }
                }
            } else {
                if (gr0 < NN)
                    *(__half2*)(outh + (size_t)gr0 * 128 + col) =
                        __floats2half2_rn(acc[mt][nt][0] * s0, acc[mt][nt][1] * s0);
                if (gr1 < NN)
                    *(__half2*)(outh + (size_t)gr1 * 128 + col) =
                        __floats2half2_rn(acc[mt][nt][2] * s1, acc[mt][nt][3] * s1);
            }
        }
    }
}

// ---------------- aggregation (fp16 xws) + relu + residual (+LN) ------------
template<bool LAST>
__global__ void agg_k(const float* __restrict__ bias,
                      const float* __restrict__ lng,
                      const float* __restrict__ lnb,
                      float* __restrict__ out) {
    int warp = threadIdx.x >> 5, lane = threadIdx.x & 31;
    int row = blockIdx.x * 8 + warp;
    if (row >= NN) return;
    const uint2* xw2 = (const uint2*)g_xwh;       // 8B = 4 halves per lane
    float4 acc = h8_to_f4(xw2[(size_t)row * 32 + lane]);   // self term
    int e = g_rowptr[row], end = g_rowptr[row + 1];
    for (; e + 4 <= end; e += 4) {
        int s0 = g_col[e], s1 = g_col[e + 1], s2 = g_col[e + 2], s3 = g_col[e + 3];
        uint2 p0 = xw2[(size_t)s0 * 32 + lane];
        uint2 p1 = xw2[(size_t)s1 * 32 + lane];
        uint2 p2 = xw2[(size_t)s2 * 32 + lane];
        uint2 p3 = xw2[(size_t)s3 * 32 + lane];
        float4 v0 = h8_to_f4(p0), v1 = h8_to_f4(p1), v2 = h8_to_f4(p2), v3 = h8_to_f4(p3);
        acc.x += (v0.x + v1.x) + (v2.x + v3.x);
        acc.y += (v0.y + v1.y) + (v2.y + v3.y);
        acc.z += (v0.z + v1.z) + (v2.z + v3.z);
        acc.w += (v0.w + v1.w) + (v2.w + v3.w);
    }
    for (; e < end; e++) {
        float4 v = h8_to_f4(xw2[(size_t)g_col[e] * 32 + lane]);
        acc.x += v.x; acc.y += v.y; acc.z += v.z; acc.w += v.w;
    }
    float d = g_dis[row];
    float4 bb = ((const float4*)bias)[lane];
    float4 xo = ((const float4*)g_x)[(size_t)row * 32 + lane];
    float4 v;
    v.x = xo.x + fmaxf(d * acc.x + bb.x, 0.f);
    v.y = xo.y + fmaxf(d * acc.y + bb.y, 0.f);
    v.z = xo.z + fmaxf(d * acc.z + bb.z, 0.f);
    v.w = xo.w + fmaxf(d * acc.w + bb.w, 0.f);
    if (!LAST) {
        ((float4*)g_x)[(size_t)row * 32 + lane] = v;
    } else {
        float s = v.x + v.y + v.z + v.w;
        float s2 = v.x * v.x + v.y * v.y + v.z * v.z + v.w * v.w;
        #pragma unroll
        for (int o = 16; o; o >>= 1) {
            s  += __shfl_xor_sync(0xffffffffu, s, o);
            s2 += __shfl_xor_sync(0xffffffffu, s2, o);
        }
        float mean = s * (1.0f / 128.0f);
        float var = s2 * (1.0f / 128.0f) - mean * mean;
        float rstd = rsqrtf(var + 1e-5f);
        float4 gg = ((const float4*)lng)[lane];
        float4 lbb = ((const float4*)lnb)[lane];
        float4 o4;
        o4.x = (v.x - mean) * rstd * gg.x + lbb.x;
        o4.y = (v.y - mean) * rstd * gg.y + lbb.y;
        o4.z = (v.z - mean) * rstd * gg.z + lbb.z;
        o4.w = (v.w - mean) * rstd * gg.w + lbb.w;
        ((float4*)out)[(size_t)row * 32 + lane] = o4;
    }
}

// ---------------- launcher --------------------------------------------------
static cudaStream_t g_s1 = nullptr;
static cudaEvent_t  g_evFork = nullptr, g_evScan = nullptr, g_evFill = nullptr;

extern "C" void kernel_launch(void* const* d_in, const int* in_sizes, int n_in,
                              void* d_out, int out_size) {
    const float* llm = (const float*)d_in[0];
    const int*   ids = (const int*)d_in[1];
    const int*   ei  = (const int*)d_in[2];
    const float* pW  = (const float*)d_in[3];
    const float* pb  = (const float*)d_in[4];
    const float* emb = (const float*)d_in[5];
    const float* gW  = (const float*)d_in[6];
    const float* gb  = (const float*)d_in[7];
    const float* lg  = (const float*)d_in[8];
    const float* lb  = (const float*)d_in[9];
    const int* src = ei;
    const int* dst = ei + EE;

    const int MB = (NN + 127) / 128;
    const int WB = (NN + 7) / 8;
    const int EB4 = (EE / 4 + 255) / 256;

    if (g_s1 == nullptr) {       // one-time host resource setup (no device mem)
        cudaStreamCreateWithFlags(&g_s1, cudaStreamNonBlocking);
        cudaEventCreateWithFlags(&g_evFork, cudaEventDisableTiming);
        cudaEventCreateWithFlags(&g_evScan, cudaEventDisableTiming);
        cudaEventCreateWithFlags(&g_evFill, cudaEventDisableTiming);
    }

    float*  d_x  = nullptr; cudaGetSymbolAddress((void**)&d_x,  g_x);
    __half* d_xw = nullptr; cudaGetSymbolAddress((void**)&d_xw, g_xwh);
    float*  d_Wp = nullptr; cudaGetSymbolAddress((void**)&d_Wp, g_Wp);
    float*  d_bp = nullptr; cudaGetSymbolAddress((void**)&d_bp, g_bp);

    // pad_k zeroes g_cnt and pads W/bias (needed by both branches)
    pad_k<<<(LLM * HID + 255) / 256, 256>>>(pW, pb);

    // ---- fork: CSR build on side stream, proj on main stream ----
    cudaEventRecord(g_evFork, 0);
    cudaStreamWaitEvent(g_s1, g_evFork, 0);

    count_k<<<EB4, 256, 0, g_s1>>>(dst);
    scan_k<<<1, 1024, 0, g_s1>>>();
    cudaEventRecord(g_evScan, g_s1);
    fill_k<<<EB4, 256, 0, g_s1>>>(src, dst);
    cudaEventRecord(g_evFill, g_s1);

    mma_gemm_k<LLM, LLM, true><<<MB, 256>>>(llm, d_Wp, d_bp, ids, emb, d_x, nullptr);

    // gemm epilogue needs g_dis (scan); agg needs g_col (fill)
    cudaStreamWaitEvent(0, g_evScan, 0);
    mma_gemm_k<HID, HID, false><<<MB, 256>>>(d_x, gW, nullptr, nullptr, nullptr,
                                             nullptr, d_xw);
    cudaStreamWaitEvent(0, g_evFill, 0);
    agg_k<false><<<WB, 256>>>(gb, nullptr, nullptr, nullptr);

    mma_gemm_k<HID, HID, false><<<MB, 256>>>(d_x, gW + (size_t)HID * HID, nullptr,
                                             nullptr, nullptr, nullptr, d_xw);
    agg_k<true><<<WB, 256>>>(gb + HID, lg, lb, (float*)d_out);
}

// round 10
// speedup vs baseline: 3.1540x; 1.0975x over previous
#include <cuda_runtime.h>
#include <cuda_fp16.h>

#define NN 50000
#define EE 600000
#define LLM 640
#define HID 128
#define PO 112
#define SD 16

typedef unsigned int uint;

#define PROJ_ITS 20
#define GCN_ITS  4
#define ITER_WORDS 4096                      // B frag words per 32-k iteration
#define PROJ_FRAG_WORDS (PROJ_ITS * ITER_WORDS)   // 81920
#define GCN_FRAG_WORDS  (GCN_ITS * ITER_WORDS)    // 16384

// ---------------- scratch (static device globals; no allocation) ------------
__device__ float  g_x[(size_t)NN * HID];
__device__ __half g_xwh[(size_t)NN * HID];   // xws = dis * (x@W), fp16
__device__ float  g_dis[NN];
__device__ __align__(16) int g_cnt[NN];
__device__ int    g_rowptr[NN + 1];
__device__ int    g_pos[NN];
__device__ __align__(16) int g_col[EE];
__device__ __align__(16) uint g_WpF[PROJ_FRAG_WORDS];     // proj B fragments (tf32)
__device__ __align__(16) uint g_WgF[2][GCN_FRAG_WORDS];   // gcn  B fragments (tf32)

__device__ __forceinline__ uint f2tf32(float x) {
    uint r;
    asm("cvt.rna.tf32.f32 %0, %1;" : "=r"(r) : "f"(x));
    return r;
}
__device__ __forceinline__ float4 h8_to_f4(uint2 p) {
    __half2 a = *(__half2*)&p.x, b = *(__half2*)&p.y;
    float2 fa = __half22float2(a), fb = __half22float2(b);
    return make_float4(fa.x, fa.y, fb.x, fb.y);
}

// ---------------- prep: B fragments (tf32, smem image) + zero counters ------
// Fragment word layout per 32-k iteration (matches smem image exactly):
//   idx = ((ntile*4 + k8)*64) + lane*2 + jj
//   k = it*32 + k8*8 + jj*4 + (lane&3),  n = ntile*8 + (lane>>2)
__global__ void prep_k(const float* __restrict__ pW, const float* __restrict__ gW) {
    int i = blockIdx.x * blockDim.x + threadIdx.x;
    if (i < NN) g_cnt[i] = 0;
    if (i < PROJ_FRAG_WORDS) {
        int it = i >> 12, word = i & 4095;
        int blk = word >> 6, rem = word & 63;
        int ntile = blk >> 2, k8 = blk & 3;
        int lane = rem >> 1, jj = rem & 1;
        int k = it * 32 + k8 * 8 + jj * 4 + (lane & 3);
        int n = ntile * 8 + (lane >> 2);
        float v = (n < PO) ? pW[k * PO + n] : 0.0f;
        g_WpF[i] = f2tf32(v);
    } else if (i < PROJ_FRAG_WORDS + 2 * GCN_FRAG_WORDS) {
        int i2 = i - PROJ_FRAG_WORDS;
        int layer = i2 >> 14;              // / GCN_FRAG_WORDS
        int w = i2 & (GCN_FRAG_WORDS - 1);
        int it = w >> 12, word = w & 4095;
        int blk = word >> 6, rem = word & 63;
        int ntile = blk >> 2, k8 = blk & 3;
        int lane = rem >> 1, jj = rem & 1;
        int k = it * 32 + k8 * 8 + jj * 4 + (lane & 3);
        int n = ntile * 8 + (lane >> 2);
        g_WgF[layer][w] = f2tf32(gW[(size_t)layer * HID * HID + k * HID + n]);
    }
}

// ---------------- CSR build (side stream) -----------------------------------
__global__ void count_k(const int* __restrict__ dst) {
    int e0 = (blockIdx.x * blockDim.x + threadIdx.x) * 4;
    if (e0 < EE) {
        int4 d = *(const int4*)(dst + e0);
        atomicAdd(&g_cnt[d.x], 1);
        atomicAdd(&g_cnt[d.y], 1);
        atomicAdd(&g_cnt[d.z], 1);
        atomicAdd(&g_cnt[d.w], 1);
    }
}

__global__ void scan_k() {
    __shared__ int warp_tot[32];
    __shared__ int carry_s;
    int tid = threadIdx.x, lane = tid & 31, w = tid >> 5;
    if (tid == 0) { carry_s = 0; g_rowptr[0] = 0; }
    __syncthreads();
    for (int base = 0; base < NN; base += 4096) {
        int i0 = base + tid * 4;
        int4 v = make_int4(0, 0, 0, 0);
        if (i0 < NN) v = *(const int4*)(g_cnt + i0);
        int s = v.x + v.y + v.z + v.w;
        int x = s;
        #pragma unroll
        for (int o = 1; o < 32; o <<= 1) {
            int y = __shfl_up_sync(0xffffffffu, x, o);
            if (lane >= o) x += y;
        }
        if (lane == 31) warp_tot[w] = x;
        __syncthreads();
        if (w == 0) {
            int t = warp_tot[lane];
            #pragma unroll
            for (int o = 1; o < 32; o <<= 1) {
                int y = __shfl_up_sync(0xffffffffu, t, o);
                if (lane >= o) t += y;
            }
            warp_tot[lane] = t;
        }
        __syncthreads();
        int woff = (w > 0) ? warp_tot[w - 1] : 0;
        int incl = x + woff + carry_s;
        int excl = incl - s;
        if (i0 < NN) {
            int p0 = excl + v.x, p1 = p0 + v.y, p2 = p1 + v.z, p3 = p2 + v.w;
            g_rowptr[i0 + 1] = p0; g_rowptr[i0 + 2] = p1;
            g_rowptr[i0 + 3] = p2; g_rowptr[i0 + 4] = p3;
            g_pos[i0] = excl; g_pos[i0 + 1] = p0; g_pos[i0 + 2] = p1; g_pos[i0 + 3] = p2;
            g_dis[i0 + 0] = rsqrtf(1.0f + (float)v.x);
            g_dis[i0 + 1] = rsqrtf(1.0f + (float)v.y);
            g_dis[i0 + 2] = rsqrtf(1.0f + (float)v.z);
            g_dis[i0 + 3] = rsqrtf(1.0f + (float)v.w);
        }
        __syncthreads();
        if (tid == 1023) carry_s = incl;
        __syncthreads();
    }
}

__global__ void fill_k(const int* __restrict__ src, const int* __restrict__ dst) {
    int e0 = (blockIdx.x * blockDim.x + threadIdx.x) * 4;
    if (e0 < EE) {
        int4 d = *(const int4*)(dst + e0);
        int4 s = *(const int4*)(src + e0);
        int p0 = atomicAdd(&g_pos[d.x], 1);
        int p1 = atomicAdd(&g_pos[d.y], 1);
        int p2 = atomicAdd(&g_pos[d.z], 1);
        int p3 = atomicAdd(&g_pos[d.w], 1);
        g_col[p0] = s.x; g_col[p1] = s.y; g_col[p2] = s.z; g_col[p3] = s.w;
    }
}

// ---------------- tf32 mma GEMM, double-buffered, cp.async B ----------------
// BM=128, BN=128, BK=32. 8 warps (2m x 4n), warp tile 64x32 = 4x4 m16n8k8.
// A: raw fp32 in smem (HW truncates to tf32, RZ). B: pre-converted fragments.
#define BSA 132
#define ASZ (32 * BSA)     // 4224 words
#define BSZ 4096           // words, contiguous fragment image

template<int K, int LDA, bool PROJ>
__global__ __launch_bounds__(256, 2) void mma_gemm_k(const float* __restrict__ A,
                                                     const uint* __restrict__ WF,
                                                     const float* __restrict__ bias,
                                                     const int* __restrict__ ids,
                                                     const float* __restrict__ emb,
                                                     float* __restrict__ outf,
                                                     __half* __restrict__ outh) {
    __shared__ __align__(16) uint As[2][ASZ];
    __shared__ __align__(16) uint Bs[2][BSZ];
    int tid = threadIdx.x;
    int lane = tid & 31, wid = tid >> 5;
    int warp_m = wid >> 2;
    int warp_n = wid & 3;
    int row0 = blockIdx.x * 128;
    const int NT = K / 32;

    float acc[4][4][4];
    #pragma unroll
    for (int mt = 0; mt < 4; mt++)
        #pragma unroll
        for (int nt = 0; nt < 4; nt++)
            #pragma unroll
            for (int j = 0; j < 4; j++) acc[mt][nt][j] = 0.0f;

    float4 va[4];

    auto loadA = [&](int k0) {
        #pragma unroll
        for (int i = 0; i < 4; i++) {
            int f = tid + i * 256;
            int r = f >> 3, c = (f & 7) * 4;
            int gr = row0 + r;
            va[i] = make_float4(0.f, 0.f, 0.f, 0.f);
            if (gr < NN) va[i] = *(const float4*)(A + (size_t)gr * LDA + k0 + c);
        }
    };
    auto storeA = [&](int buf) {          // raw fp32 bits; HW reads tf32 (RZ)
        #pragma unroll
        for (int i = 0; i < 4; i++) {
            int f = tid + i * 256;
            int r = f >> 3, c = (f & 7) * 4;
            int mtile = r >> 4, rloc = r & 15;
            int j = (rloc >> 3) + 2 * ((c >> 2) & 1);
            int tb = (rloc & 7) * 4;
            uint* dst = As[buf] + ((mtile << 2) + (c >> 3)) * BSA + j;
            dst[(tb + 0) * 4] = __float_as_uint(va[i].x);
            dst[(tb + 1) * 4] = __float_as_uint(va[i].y);
            dst[(tb + 2) * 4] = __float_as_uint(va[i].z);
            dst[(tb + 3) * 4] = __float_as_uint(va[i].w);
        }
    };
    auto stageB = [&](int it, int buf) {  // cp.async 64B/thread, coalesced
        const uint* src = WF + (size_t)it * ITER_WORDS + tid * 16;
        uint sm = (uint)__cvta_generic_to_shared(Bs[buf] + tid * 16);
        #pragma unroll
        for (int i = 0; i < 4; i++)
            asm volatile("cp.async.ca.shared.global [%0], [%1], 16;"
                         :: "r"(sm + i * 16), "l"(src + i * 4));
        asm volatile("cp.async.commit_group;");
    };

    // ---- prologue ----
    loadA(0);
    stageB(0, 0);
    storeA(0);
    asm volatile("cp.async.wait_group 0;" ::: "memory");
    __syncthreads();

    for (int it = 0; it < NT; it++) {
        int cur = it & 1;
        if (it + 1 < NT) {
            stageB(it + 1, cur ^ 1);      // prior readers of buf nxt done before last sync
            loadA((it + 1) * 32);         // LDG in flight during mma
        }

        #pragma unroll
        for (int k8 = 0; k8 < 4; k8++) {
            uint4 a[4];
            uint2 b[4];
            #pragma unroll
            for (int mt = 0; mt < 4; mt++)
                a[mt] = *(const uint4*)(As[cur] + (((warp_m * 4 + mt) << 2) + k8) * BSA + lane * 4);
            #pragma unroll
            for (int nt = 0; nt < 4; nt++)
                b[nt] = *(const uint2*)(Bs[cur] + (((warp_n * 4 + nt) << 2) + k8) * 64 + lane * 2);
            #pragma unroll
            for (int mt = 0; mt < 4; mt++)
                #pragma unroll
                for (int nt = 0; nt < 4; nt++) {
                    asm volatile(
                        "mma.sync.aligned.m16n8k8.row.col.f32.tf32.tf32.f32 "
                        "{%0,%1,%2,%3}, {%4,%5,%6,%7}, {%8,%9}, {%0,%1,%2,%3};"
                        : "+f"(acc[mt][nt][0]), "+f"(acc[mt][nt][1]),
                          "+f"(acc[mt][nt][2]), "+f"(acc[mt][nt][3])
                        : "r"(a[mt].x), "r"(a[mt].y), "r"(a[mt].z), "r"(a[mt].w),
                          "r"(b[nt].x), "r"(b[nt].y));
                }
        }

        if (it + 1 < NT) {
            storeA(cur ^ 1);              // writes other buffer; mma readers of cur unaffected
            asm volatile("cp.async.wait_group 0;" ::: "memory");
            __syncthreads();
        }
    }

    // ---- epilogue ----
    #pragma unroll
    for (int mt = 0; mt < 4; mt++) {
        int gr0 = row0 + warp_m * 64 + mt * 16 + (lane >> 2);
        int gr1 = gr0 + 8;
        float s0 = 1.f, s1 = 1.f;
        if (!PROJ) {
            if (gr0 < NN) s0 = g_dis[gr0];
            if (gr1 < NN) s1 = g_dis[gr1];
        }
        #pragma unroll
        for (int nt = 0; nt < 4; nt++) {
            int col = warp_n * 32 + nt * 8 + (lane & 3) * 2;
            if (PROJ) {
                if (col < PO) {
                    float b0 = bias[col], b1 = bias[col + 1];
                    if (gr0 < NN)
                        *(float2*)(outf + (size_t)gr0 * 128 + col) =
                            make_float2(acc[mt][nt][0] + b0, acc[mt][nt][1] + b1);
                    if (gr1 < NN)
                        *(float2*)(outf + (size_t)gr1 * 128 + col) =
                            make_float2(acc[mt][nt][2] + b0, acc[mt][nt][3] + b1);
                } else {
                    int t = col - PO;
                    if (gr0 < NN) {
                        float2 ev = *(const float2*)(emb + ids[gr0] * SD + t);
                        *(float2*)(outf + (size_t)gr0 * 128 + col) = ev;
                    }
                    if (gr1 < NN) {
                        float2 ev = *(const float2*)(emb + ids[gr1] * SD + t);
                        *(float2*)(outf + (size_t)gr1 * 128 + col) = ev;
                    }
                }
            } else {
                if (gr0 < NN)
                    *(__half2*)(outh + (size_t)gr0 * 128 + col) =
                        __floats2half2_rn(acc[mt][nt][0] * s0, acc[mt][nt][1] * s0);
                if (gr1 < NN)
                    *(__half2*)(outh + (size_t)gr1 * 128 + col) =
                        __floats2half2_rn(acc[mt][nt][2] * s1, acc[mt][nt][3] * s1);
            }
        }
    }
}

// ---------------- aggregation (fp16 xws) + relu + residual (+LN) ------------
template<bool LAST>
__global__ void agg_k(const float* __restrict__ bias,
                      const float* __restrict__ lng,
                      const float* __restrict__ lnb,
                      float* __restrict__ out) {
    int warp = threadIdx.x >> 5, lane = threadIdx.x & 31;
    int row = blockIdx.x * 8 + warp;
    if (row >= NN) return;
    const uint2* xw2 = (const uint2*)g_xwh;
    float4 acc = h8_to_f4(xw2[(size_t)row * 32 + lane]);   // self term
    int e = g_rowptr[row], end = g_rowptr[row + 1];
    for (; e + 8 <= end; e += 8) {
        int s0 = g_col[e],     s1 = g_col[e + 1], s2 = g_col[e + 2], s3 = g_col[e + 3];
        int s4 = g_col[e + 4], s5 = g_col[e + 5], s6 = g_col[e + 6], s7 = g_col[e + 7];
        float4 v0 = h8_to_f4(xw2[(size_t)s0 * 32 + lane]);
        float4 v1 = h8_to_f4(xw2[(size_t)s1 * 32 + lane]);
        float4 v2 = h8_to_f4(xw2[(size_t)s2 * 32 + lane]);
        float4 v3 = h8_to_f4(xw2[(size_t)s3 * 32 + lane]);
        float4 v4 = h8_to_f4(xw2[(size_t)s4 * 32 + lane]);
        float4 v5 = h8_to_f4(xw2[(size_t)s5 * 32 + lane]);
        float4 v6 = h8_to_f4(xw2[(size_t)s6 * 32 + lane]);
        float4 v7 = h8_to_f4(xw2[(size_t)s7 * 32 + lane]);
        acc.x += ((v0.x + v1.x) + (v2.x + v3.x)) + ((v4.x + v5.x) + (v6.x + v7.x));
        acc.y += ((v0.y + v1.y) + (v2.y + v3.y)) + ((v4.y + v5.y) + (v6.y + v7.y));
        acc.z += ((v0.z + v1.z) + (v2.z + v3.z)) + ((v4.z + v5.z) + (v6.z + v7.z));
        acc.w += ((v0.w + v1.w) + (v2.w + v3.w)) + ((v4.w + v5.w) + (v6.w + v7.w));
    }
    for (; e + 4 <= end; e += 4) {
        int s0 = g_col[e], s1 = g_col[e + 1], s2 = g_col[e + 2], s3 = g_col[e + 3];
        float4 v0 = h8_to_f4(xw2[(size_t)s0 * 32 + lane]);
        float4 v1 = h8_to_f4(xw2[(size_t)s1 * 32 + lane]);
        float4 v2 = h8_to_f4(xw2[(size_t)s2 * 32 + lane]);
        float4 v3 = h8_to_f4(xw2[(size_t)s3 * 32 + lane]);
        acc.x += (v0.x + v1.x) + (v2.x + v3.x);
        acc.y += (v0.y + v1.y) + (v2.y + v3.y);
        acc.z += (v0.z + v1.z) + (v2.z + v3.z);
        acc.w += (v0.w + v1.w) + (v2.w + v3.w);
    }
    for (; e < end; e++) {
        float4 v = h8_to_f4(xw2[(size_t)g_col[e] * 32 + lane]);
        acc.x += v.x; acc.y += v.y; acc.z += v.z; acc.w += v.w;
    }
    float d = g_dis[row];
    float4 bb = ((const float4*)bias)[lane];
    float4 xo = ((const float4*)g_x)[(size_t)row * 32 + lane];
    float4 v;
    v.x = xo.x + fmaxf(d * acc.x + bb.x, 0.f);
    v.y = xo.y + fmaxf(d * acc.y + bb.y, 0.f);
    v.z = xo.z + fmaxf(d * acc.z + bb.z, 0.f);
    v.w = xo.w + fmaxf(d * acc.w + bb.w, 0.f);
    if (!LAST) {
        ((float4*)g_x)[(size_t)row * 32 + lane] = v;
    } else {
        float s = v.x + v.y + v.z + v.w;
        float s2 = v.x * v.x + v.y * v.y + v.z * v.z + v.w * v.w;
        #pragma unroll
        for (int o = 16; o; o >>= 1) {
            s  += __shfl_xor_sync(0xffffffffu, s, o);
            s2 += __shfl_xor_sync(0xffffffffu, s2, o);
        }
        float mean = s * (1.0f / 128.0f);
        float var = s2 * (1.0f / 128.0f) - mean * mean;
        float rstd = rsqrtf(var + 1e-5f);
        float4 gg = ((const float4*)lng)[lane];
        float4 lbb = ((const float4*)lnb)[lane];
        float4 o4;
        o4.x = (v.x - mean) * rstd * gg.x + lbb.x;
        o4.y = (v.y - mean) * rstd * gg.y + lbb.y;
        o4.z = (v.z - mean) * rstd * gg.z + lbb.z;
        o4.w = (v.w - mean) * rstd * gg.w + lbb.w;
        ((float4*)out)[(size_t)row * 32 + lane] = o4;
    }
}

// ---------------- launcher --------------------------------------------------
static cudaStream_t g_s1 = nullptr;
static cudaEvent_t  g_evFork = nullptr, g_evScan = nullptr, g_evFill = nullptr;

extern "C" void kernel_launch(void* const* d_in, const int* in_sizes, int n_in,
                              void* d_out, int out_size) {
    const float* llm = (const float*)d_in[0];
    const int*   ids = (const int*)d_in[1];
    const int*   ei  = (const int*)d_in[2];
    const float* pW  = (const float*)d_in[3];
    const float* pb  = (const float*)d_in[4];
    const float* emb = (const float*)d_in[5];
    const float* gW  = (const float*)d_in[6];
    const float* gb  = (const float*)d_in[7];
    const float* lg  = (const float*)d_in[8];
    const float* lb  = (const float*)d_in[9];
    const int* src = ei;
    const int* dst = ei + EE;

    const int MB = (NN + 127) / 128;
    const int WB = (NN + 7) / 8;
    const int EB4 = (EE / 4 + 255) / 256;
    const int PB = (PROJ_FRAG_WORDS + 2 * GCN_FRAG_WORDS + 255) / 256;  // 448

    if (g_s1 == nullptr) {
        cudaStreamCreateWithFlags(&g_s1, cudaStreamNonBlocking);
        cudaEventCreateWithFlags(&g_evFork, cudaEventDisableTiming);
        cudaEventCreateWithFlags(&g_evScan, cudaEventDisableTiming);
        cudaEventCreateWithFlags(&g_evFill, cudaEventDisableTiming);
    }

    float*  d_x  = nullptr; cudaGetSymbolAddress((void**)&d_x,  g_x);
    __half* d_xw = nullptr; cudaGetSymbolAddress((void**)&d_xw, g_xwh);
    uint*   d_WpF = nullptr; cudaGetSymbolAddress((void**)&d_WpF, g_WpF);
    uint*   d_WgF = nullptr; cudaGetSymbolAddress((void**)&d_WgF, g_WgF);

    // prep: B fragments + zero g_cnt
    prep_k<<<PB, 256>>>(pW, gW);

    // ---- fork: CSR build on side stream ----
    cudaEventRecord(g_evFork, 0);
    cudaStreamWaitEvent(g_s1, g_evFork, 0);

    count_k<<<EB4, 256, 0, g_s1>>>(dst);
    scan_k<<<1, 1024, 0, g_s1>>>();
    cudaEventRecord(g_evScan, g_s1);
    fill_k<<<EB4, 256, 0, g_s1>>>(src, dst);
    cudaEventRecord(g_evFill, g_s1);

    mma_gemm_k<LLM, LLM, true><<<MB, 256>>>(llm, d_WpF, pb, ids, emb, d_x, nullptr);

    cudaStreamWaitEvent(0, g_evScan, 0);
    mma_gemm_k<HID, HID, false><<<MB, 256>>>(d_x, d_WgF, nullptr, nullptr, nullptr,
                                             nullptr, d_xw);
    cudaStreamWaitEvent(0, g_evFill, 0);
    agg_k<false><<<WB, 256>>>(gb, nullptr, nullptr, nullptr);

    mma_gemm_k<HID, HID, false><<<MB, 256>>>(d_x, d_WgF + GCN_FRAG_WORDS, nullptr,
                                             nullptr, nullptr, nullptr, d_xw);
    agg_k<true><<<WB, 256>>>(gb + HID, lg, lb, (float*)d_out);
}

// round 11
// speedup vs baseline: 3.4922x; 1.1072x over previous
#include <cuda_runtime.h>
#include <cuda_fp16.h>

#define NN 50000
#define EE 600000
#define LLM 640
#define HID 128
#define PO 112
#define SD 16

typedef unsigned int uint;

#define PROJ_ITS 20
#define GCN_ITS  4
#define ITER_WORDS 4096
#define PROJ_FRAG_WORDS (PROJ_ITS * ITER_WORDS)
#define GCN_FRAG_WORDS  (GCN_ITS * ITER_WORDS)

// ---------------- scratch (static device globals; no allocation) ------------
__device__ float  g_x[(size_t)NN * HID];
__device__ __align__(16) __half g_xwh[(size_t)NN * HID];
__device__ float  g_dis[NN];
__device__ __align__(16) int g_cnt[NN];
__device__ int    g_rowptr[NN + 1];
__device__ int    g_pos[NN];
__device__ __align__(16) int g_col[EE];
__device__ __align__(16) uint g_WpF[PROJ_FRAG_WORDS];
__device__ __align__(16) uint g_WgF[2][GCN_FRAG_WORDS];

__device__ __forceinline__ uint f2tf32(float x) {
    uint r;
    asm("cvt.rna.tf32.f32 %0, %1;" : "=r"(r) : "f"(x));
    return r;
}
__device__ __forceinline__ float4 h8_to_f4(uint a, uint b) {
    __half2 ha = *(__half2*)&a, hb = *(__half2*)&b;
    float2 fa = __half22float2(ha), fb = __half22float2(hb);
    return make_float4(fa.x, fa.y, fb.x, fb.y);
}

// ---------------- zero counters (side stream, before count) -----------------
__global__ void zero_cnt_k() {
    int i = blockIdx.x * blockDim.x + threadIdx.x;
    if (i < NN) g_cnt[i] = 0;
}

// ---------------- prep: B fragments (tf32, smem image) ----------------------
__global__ void prep_k(const float* __restrict__ pW, const float* __restrict__ gW) {
    int i = blockIdx.x * blockDim.x + threadIdx.x;
    if (i < PROJ_FRAG_WORDS) {
        int it = i >> 12, word = i & 4095;
        int blk = word >> 6, rem = word & 63;
        int ntile = blk >> 2, k8 = blk & 3;
        int lane = rem >> 1, jj = rem & 1;
        int k = it * 32 + k8 * 8 + jj * 4 + (lane & 3);
        int n = ntile * 8 + (lane >> 2);
        float v = (n < PO) ? pW[k * PO + n] : 0.0f;
        g_WpF[i] = f2tf32(v);
    } else if (i < PROJ_FRAG_WORDS + 2 * GCN_FRAG_WORDS) {
        int i2 = i - PROJ_FRAG_WORDS;
        int layer = i2 >> 14;
        int w = i2 & (GCN_FRAG_WORDS - 1);
        int it = w >> 12, word = w & 4095;
        int blk = word >> 6, rem = word & 63;
        int ntile = blk >> 2, k8 = blk & 3;
        int lane = rem >> 1, jj = rem & 1;
        int k = it * 32 + k8 * 8 + jj * 4 + (lane & 3);
        int n = ntile * 8 + (lane >> 2);
        g_WgF[layer][w] = f2tf32(gW[(size_t)layer * HID * HID + k * HID + n]);
    }
}

// ---------------- CSR build (side stream) -----------------------------------
__global__ void count_k(const int* __restrict__ dst) {
    int e0 = (blockIdx.x * blockDim.x + threadIdx.x) * 4;
    if (e0 < EE) {
        int4 d = *(const int4*)(dst + e0);
        atomicAdd(&g_cnt[d.x], 1);
        atomicAdd(&g_cnt[d.y], 1);
        atomicAdd(&g_cnt[d.z], 1);
        atomicAdd(&g_cnt[d.w], 1);
    }
}

__global__ void scan_k() {
    __shared__ int warp_tot[32];
    __shared__ int carry_s;
    int tid = threadIdx.x, lane = tid & 31, w = tid >> 5;
    if (tid == 0) { carry_s = 0; g_rowptr[0] = 0; }
    __syncthreads();
    for (int base = 0; base < NN; base += 4096) {
        int i0 = base + tid * 4;
        int4 v = make_int4(0, 0, 0, 0);
        if (i0 < NN) v = *(const int4*)(g_cnt + i0);
        int s = v.x + v.y + v.z + v.w;
        int x = s;
        #pragma unroll
        for (int o = 1; o < 32; o <<= 1) {
            int y = __shfl_up_sync(0xffffffffu, x, o);
            if (lane >= o) x += y;
        }
        if (lane == 31) warp_tot[w] = x;
        __syncthreads();
        if (w == 0) {
            int t = warp_tot[lane];
            #pragma unroll
            for (int o = 1; o < 32; o <<= 1) {
                int y = __shfl_up_sync(0xffffffffu, t, o);
                if (lane >= o) t += y;
            }
            warp_tot[lane] = t;
        }
        __syncthreads();
        int woff = (w > 0) ? warp_tot[w - 1] : 0;
        int incl = x + woff + carry_s;
        int excl = incl - s;
        if (i0 < NN) {
            int p0 = excl + v.x, p1 = p0 + v.y, p2 = p1 + v.z, p3 = p2 + v.w;
            g_rowptr[i0 + 1] = p0; g_rowptr[i0 + 2] = p1;
            g_rowptr[i0 + 3] = p2; g_rowptr[i0 + 4] = p3;
            g_pos[i0] = excl; g_pos[i0 + 1] = p0; g_pos[i0 + 2] = p1; g_pos[i0 + 3] = p2;
            g_dis[i0 + 0] = rsqrtf(1.0f + (float)v.x);
            g_dis[i0 + 1] = rsqrtf(1.0f + (float)v.y);
            g_dis[i0 + 2] = rsqrtf(1.0f + (float)v.z);
            g_dis[i0 + 3] = rsqrtf(1.0f + (float)v.w);
        }
        __syncthreads();
        if (tid == 1023) carry_s = incl;
        __syncthreads();
    }
}

__global__ void fill_k(const int* __restrict__ src, const int* __restrict__ dst) {
    int e0 = (blockIdx.x * blockDim.x + threadIdx.x) * 4;
    if (e0 < EE) {
        int4 d = *(const int4*)(dst + e0);
        int4 s = *(const int4*)(src + e0);
        int p0 = atomicAdd(&g_pos[d.x], 1);
        int p1 = atomicAdd(&g_pos[d.y], 1);
        int p2 = atomicAdd(&g_pos[d.z], 1);
        int p3 = atomicAdd(&g_pos[d.w], 1);
        g_col[p0] = s.x; g_col[p1] = s.y; g_col[p2] = s.z; g_col[p3] = s.w;
    }
}

// ---------------- tf32 mma GEMM, double-buffered, cp.async B ----------------
#define BSA 132
#define ASZ (32 * BSA)
#define BSZ 4096

template<int K, int LDA, bool PROJ>
__global__ __launch_bounds__(256, 2) void mma_gemm_k(const float* __restrict__ A,
                                                     const uint* __restrict__ WF,
                                                     const float* __restrict__ bias,
                                                     const int* __restrict__ ids,
                                                     const float* __restrict__ emb,
                                                     float* __restrict__ outf,
                                                     __half* __restrict__ outh) {
    __shared__ __align__(16) uint As[2][ASZ];
    __shared__ __align__(16) uint Bs[2][BSZ];
    int tid = threadIdx.x;
    int lane = tid & 31, wid = tid >> 5;
    int warp_m = wid >> 2;
    int warp_n = wid & 3;
    int row0 = blockIdx.x * 128;
    const int NT = K / 32;

    float acc[4][4][4];
    #pragma unroll
    for (int mt = 0; mt < 4; mt++)
        #pragma unroll
        for (int nt = 0; nt < 4; nt++)
            #pragma unroll
            for (int j = 0; j < 4; j++) acc[mt][nt][j] = 0.0f;

    float4 va[4];

    auto loadA = [&](int k0) {
        #pragma unroll
        for (int i = 0; i < 4; i++) {
            int f = tid + i * 256;
            int r = f >> 3, c = (f & 7) * 4;
            int gr = row0 + r;
            va[i] = make_float4(0.f, 0.f, 0.f, 0.f);
            if (gr < NN) va[i] = *(const float4*)(A + (size_t)gr * LDA + k0 + c);
        }
    };
    auto storeA = [&](int buf) {
        #pragma unroll
        for (int i = 0; i < 4; i++) {
            int f = tid + i * 256;
            int r = f >> 3, c = (f & 7) * 4;
            int mtile = r >> 4, rloc = r & 15;
            int j = (rloc >> 3) + 2 * ((c >> 2) & 1);
            int tb = (rloc & 7) * 4;
            uint* dst = As[buf] + ((mtile << 2) + (c >> 3)) * BSA + j;
            dst[(tb + 0) * 4] = __float_as_uint(va[i].x);
            dst[(tb + 1) * 4] = __float_as_uint(va[i].y);
            dst[(tb + 2) * 4] = __float_as_uint(va[i].z);
            dst[(tb + 3) * 4] = __float_as_uint(va[i].w);
        }
    };
    auto stageB = [&](int it, int buf) {
        const uint* src = WF + (size_t)it * ITER_WORDS + tid * 16;
        uint sm = (uint)__cvta_generic_to_shared(Bs[buf] + tid * 16);
        #pragma unroll
        for (int i = 0; i < 4; i++)
            asm volatile("cp.async.ca.shared.global [%0], [%1], 16;"
                         :: "r"(sm + i * 16), "l"(src + i * 4));
        asm volatile("cp.async.commit_group;");
    };

    loadA(0);
    stageB(0, 0);
    storeA(0);
    asm volatile("cp.async.wait_group 0;" ::: "memory");
    __syncthreads();

    for (int it = 0; it < NT; it++) {
        int cur = it & 1;
        if (it + 1 < NT) {
            stageB(it + 1, cur ^ 1);
            loadA((it + 1) * 32);
        }

        #pragma unroll
        for (int k8 = 0; k8 < 4; k8++) {
            uint4 a[4];
            uint2 b[4];
            #pragma unroll
            for (int mt = 0; mt < 4; mt++)
                a[mt] = *(const uint4*)(As[cur] + (((warp_m * 4 + mt) << 2) + k8) * BSA + lane * 4);
            #pragma unroll
            for (int nt = 0; nt < 4; nt++)
                b[nt] = *(const uint2*)(Bs[cur] + (((warp_n * 4 + nt) << 2) + k8) * 64 + lane * 2);
            #pragma unroll
            for (int mt = 0; mt < 4; mt++)
                #pragma unroll
                for (int nt = 0; nt < 4; nt++) {
                    asm volatile(
                        "mma.sync.aligned.m16n8k8.row.col.f32.tf32.tf32.f32 "
                        "{%0,%1,%2,%3}, {%4,%5,%6,%7}, {%8,%9}, {%0,%1,%2,%3};"
                        : "+f"(acc[mt][nt][0]), "+f"(acc[mt][nt][1]),
                          "+f"(acc[mt][nt][2]), "+f"(acc[mt][nt][3])
                        : "r"(a[mt].x), "r"(a[mt].y), "r"(a[mt].z), "r"(a[mt].w),
                          "r"(b[nt].x), "r"(b[nt].y));
                }
        }

        if (it + 1 < NT) {
            storeA(cur ^ 1);
            asm volatile("cp.async.wait_group 0;" ::: "memory");
            __syncthreads();
        }
    }

    #pragma unroll
    for (int mt = 0; mt < 4; mt++) {
        int gr0 = row0 + warp_m * 64 + mt * 16 + (lane >> 2);
        int gr1 = gr0 + 8;
        float s0 = 1.f, s1 = 1.f;
        if (!PROJ) {
            if (gr0 < NN) s0 = g_dis[gr0];
            if (gr1 < NN) s1 = g_dis[gr1];
        }
        #pragma unroll
        for (int nt = 0; nt < 4; nt++) {
            int col = warp_n * 32 + nt * 8 + (lane & 3) * 2;
            if (PROJ) {
                if (col < PO) {
                    float b0 = bias[col], b1 = bias[col + 1];
                    if (gr0 < NN)
                        *(float2*)(outf + (size_t)gr0 * 128 + col) =
                            make_float2(acc[mt][nt][0] + b0, acc[mt][nt][1] + b1);
                    if (gr1 < NN)
                        *(float2*)(outf + (size_t)gr1 * 128 + col) =
                            make_float2(acc[mt][nt][2] + b0, acc[mt][nt][3] + b1);
                } else {
                    int t = col - PO;
                    if (gr0 < NN) {
                        float2 ev = *(const float2*)(emb + ids[gr0] * SD + t);
                        *(float2*)(outf + (size_t)gr0 * 128 + col) = ev;
                    }
                    if (gr1 < NN) {
                        float2 ev = *(const float2*)(emb + ids[gr1] * SD + t);
                        *(float2*)(outf + (size_t)gr1 * 128 + col) = ev;
                    }
                }
            } else {
                if (gr0 < NN)
                    *(__half2*)(outh + (size_t)gr0 * 128 + col) =
                        __floats2half2_rn(acc[mt][nt][0] * s0, acc[mt][nt][1] * s0);
                if (gr1 < NN)
                    *(__half2*)(outh + (size_t)gr1 * 128 + col) =
                        __floats2half2_rn(acc[mt][nt][2] * s1, acc[mt][nt][3] * s1);
            }
        }
    }
}

// ---------------- aggregation: half-warp per row (2 rows/warp) --------------
// Lane hl (0..15) covers 8 cols: halves [hl*8, hl*8+8) = one uint4 per row.
template<bool LAST>
__global__ void agg_k(const float* __restrict__ bias,
                      const float* __restrict__ lng,
                      const float* __restrict__ lnb,
                      float* __restrict__ out) {
    int warp = threadIdx.x >> 5, lane = threadIdx.x & 31;
    int half = lane >> 4, hl = lane & 15;
    int row = blockIdx.x * 16 + warp * 2 + half;
    if (row >= NN) return;
    const uint4* xw4 = (const uint4*)g_xwh;      // 8 halves per uint4, 16/row
    size_t rb = (size_t)row * 16 + hl;
    uint4 ps = xw4[rb];                           // self term
    float4 a0 = h8_to_f4(ps.x, ps.y);
    float4 a1 = h8_to_f4(ps.z, ps.w);
    int e = g_rowptr[row], end = g_rowptr[row + 1];
    for (; e + 8 <= end; e += 8) {
        int s0 = g_col[e],     s1 = g_col[e + 1], s2 = g_col[e + 2], s3 = g_col[e + 3];
        int s4 = g_col[e + 4], s5 = g_col[e + 5], s6 = g_col[e + 6], s7 = g_col[e + 7];
        uint4 q0 = xw4[(size_t)s0 * 16 + hl];
        uint4 q1 = xw4[(size_t)s1 * 16 + hl];
        uint4 q2 = xw4[(size_t)s2 * 16 + hl];
        uint4 q3 = xw4[(size_t)s3 * 16 + hl];
        uint4 q4 = xw4[(size_t)s4 * 16 + hl];
        uint4 q5 = xw4[(size_t)s5 * 16 + hl];
        uint4 q6 = xw4[(size_t)s6 * 16 + hl];
        uint4 q7 = xw4[(size_t)s7 * 16 + hl];
        float4 u;
        u = h8_to_f4(q0.x, q0.y); a0.x += u.x; a0.y += u.y; a0.z += u.z; a0.w += u.w;
        u = h8_to_f4(q0.z, q0.w); a1.x += u.x; a1.y += u.y; a1.z += u.z; a1.w += u.w;
        u = h8_to_f4(q1.x, q1.y); a0.x += u.x; a0.y += u.y; a0.z += u.z; a0.w += u.w;
        u = h8_to_f4(q1.z, q1.w); a1.x += u.x; a1.y += u.y; a1.z += u.z; a1.w += u.w;
        u = h8_to_f4(q2.x, q2.y); a0.x += u.x; a0.y += u.y; a0.z += u.z; a0.w += u.w;
        u = h8_to_f4(q2.z, q2.w); a1.x += u.x; a1.y += u.y; a1.z += u.z; a1.w += u.w;
        u = h8_to_f4(q3.x, q3.y); a0.x += u.x; a0.y += u.y; a0.z += u.z; a0.w += u.w;
        u = h8_to_f4(q3.z, q3.w); a1.x += u.x; a1.y += u.y; a1.z += u.z; a1.w += u.w;
        u = h8_to_f4(q4.x, q4.y); a0.x += u.x; a0.y += u.y; a0.z += u.z; a0.w += u.w;
        u = h8_to_f4(q4.z, q4.w); a1.x += u.x; a1.y += u.y; a1.z += u.z; a1.w += u.w;
        u = h8_to_f4(q5.x, q5.y); a0.x += u.x; a0.y += u.y; a0.z += u.z; a0.w += u.w;
        u = h8_to_f4(q5.z, q5.w); a1.x += u.x; a1.y += u.y; a1.z += u.z; a1.w += u.w;
        u = h8_to_f4(q6.x, q6.y); a0.x += u.x; a0.y += u.y; a0.z += u.z; a0.w += u.w;
        u = h8_to_f4(q6.z, q6.w); a1.x += u.x; a1.y += u.y; a1.z += u.z; a1.w += u.w;
        u = h8_to_f4(q7.x, q7.y); a0.x += u.x; a0.y += u.y; a0.z += u.z; a0.w += u.w;
        u = h8_to_f4(q7.z, q7.w); a1.x += u.x; a1.y += u.y; a1.z += u.z; a1.w += u.w;
    }
    for (; e + 4 <= end; e += 4) {
        int s0 = g_col[e], s1 = g_col[e + 1], s2 = g_col[e + 2], s3 = g_col[e + 3];
        uint4 q0 = xw4[(size_t)s0 * 16 + hl];
        uint4 q1 = xw4[(size_t)s1 * 16 + hl];
        uint4 q2 = xw4[(size_t)s2 * 16 + hl];
        uint4 q3 = xw4[(size_t)s3 * 16 + hl];
        float4 u;
        u = h8_to_f4(q0.x, q0.y); a0.x += u.x; a0.y += u.y; a0.z += u.z; a0.w += u.w;
        u = h8_to_f4(q0.z, q0.w); a1.x += u.x; a1.y += u.y; a1.z += u.z; a1.w += u.w;
        u = h8_to_f4(q1.x, q1.y); a0.x += u.x; a0.y += u.y; a0.z += u.z; a0.w += u.w;
        u = h8_to_f4(q1.z, q1.w); a1.x += u.x; a1.y += u.y; a1.z += u.z; a1.w += u.w;
        u = h8_to_f4(q2.x, q2.y); a0.x += u.x; a0.y += u.y; a0.z += u.z; a0.w += u.w;
        u = h8_to_f4(q2.z, q2.w); a1.x += u.x; a1.y += u.y; a1.z += u.z; a1.w += u.w;
        u = h8_to_f4(q3.x, q3.y); a0.x += u.x; a0.y += u.y; a0.z += u.z; a0.w += u.w;
        u = h8_to_f4(q3.z, q3.w); a1.x += u.x; a1.y += u.y; a1.z += u.z; a1.w += u.w;
    }
    for (; e < end; e++) {
        uint4 q = xw4[(size_t)g_col[e] * 16 + hl];
        float4 u;
        u = h8_to_f4(q.x, q.y); a0.x += u.x; a0.y += u.y; a0.z += u.z; a0.w += u.w;
        u = h8_to_f4(q.z, q.w); a1.x += u.x; a1.y += u.y; a1.z += u.z; a1.w += u.w;
    }
    float d = g_dis[row];
    const float4* b4 = (const float4*)bias;
    float4 bb0 = b4[hl * 2], bb1 = b4[hl * 2 + 1];
    const float4* x4 = (const float4*)g_x;
    float4 x0 = x4[(size_t)row * 32 + hl * 2];
    float4 x1 = x4[(size_t)row * 32 + hl * 2 + 1];
    float4 v0, v1;
    v0.x = x0.x + fmaxf(d * a0.x + bb0.x, 0.f);
    v0.y = x0.y + fmaxf(d * a0.y + bb0.y, 0.f);
    v0.z = x0.z + fmaxf(d * a0.z + bb0.z, 0.f);
    v0.w = x0.w + fmaxf(d * a0.w + bb0.w, 0.f);
    v1.x = x1.x + fmaxf(d * a1.x + bb1.x, 0.f);
    v1.y = x1.y + fmaxf(d * a1.y + bb1.y, 0.f);
    v1.z = x1.z + fmaxf(d * a1.z + bb1.z, 0.f);
    v1.w = x1.w + fmaxf(d * a1.w + bb1.w, 0.f);
    if (!LAST) {
        ((float4*)g_x)[(size_t)row * 32 + hl * 2] = v0;
        ((float4*)g_x)[(size_t)row * 32 + hl * 2 + 1] = v1;
    } else {
        float s  = (v0.x + v0.y + v0.z + v0.w) + (v1.x + v1.y + v1.z + v1.w);
        float s2 = (v0.x * v0.x + v0.y * v0.y + v0.z * v0.z + v0.w * v0.w)
                 + (v1.x * v1.x + v1.y * v1.y + v1.z * v1.z + v1.w * v1.w);
        #pragma unroll
        for (int o = 8; o; o >>= 1) {     // reduce within the 16-lane half
            s  += __shfl_xor_sync(0xffffffffu, s, o);
            s2 += __shfl_xor_sync(0xffffffffu, s2, o);
        }
        float mean = s * (1.0f / 128.0f);
        float var = s2 * (1.0f / 128.0f) - mean * mean;
        float rstd = rsqrtf(var + 1e-5f);
        const float4* g4 = (const float4*)lng;
        const float4* lb4 = (const float4*)lnb;
        float4 gg0 = g4[hl * 2], gg1 = g4[hl * 2 + 1];
        float4 lb0 = lb4[hl * 2], lb1 = lb4[hl * 2 + 1];
        float4 o0, o1;
        o0.x = (v0.x - mean) * rstd * gg0.x + lb0.x;
        o0.y = (v0.y - mean) * rstd * gg0.y + lb0.y;
        o0.z = (v0.z - mean) * rstd * gg0.z + lb0.z;
        o0.w = (v0.w - mean) * rstd * gg0.w + lb0.w;
        o1.x = (v1.x - mean) * rstd * gg1.x + lb1.x;
        o1.y = (v1.y - mean) * rstd * gg1.y + lb1.y;
        o1.z = (v1.z - mean) * rstd * gg1.z + lb1.z;
        o1.w = (v1.w - mean) * rstd * gg1.w + lb1.w;
        ((float4*)out)[(size_t)row * 32 + hl * 2] = o0;
        ((float4*)out)[(size_t)row * 32 + hl * 2 + 1] = o1;
    }
}

// ---------------- launcher --------------------------------------------------
static cudaStream_t g_s1 = nullptr;
static cudaEvent_t  g_evFork = nullptr, g_evScan = nullptr, g_evFill = nullptr;

extern "C" void kernel_launch(void* const* d_in, const int* in_sizes, int n_in,
                              void* d_out, int out_size) {
    const float* llm = (const float*)d_in[0];
    const int*   ids = (const int*)d_in[1];
    const int*   ei  = (const int*)d_in[2];
    const float* pW  = (const float*)d_in[3];
    const float* pb  = (const float*)d_in[4];
    const float* emb = (const float*)d_in[5];
    const float* gW  = (const float*)d_in[6];
    const float* gb  = (const float*)d_in[7];
    const float* lg  = (const float*)d_in[8];
    const float* lb  = (const float*)d_in[9];
    const int* src = ei;
    const int* dst = ei + EE;

    const int MB = (NN + 127) / 128;
    const int HB = (NN + 15) / 16;            // half-warp-per-row agg blocks
    const int EB4 = (EE / 4 + 255) / 256;
    const int PB = (PROJ_FRAG_WORDS + 2 * GCN_FRAG_WORDS + 255) / 256;

    if (g_s1 == nullptr) {
        cudaStreamCreateWithFlags(&g_s1, cudaStreamNonBlocking);
        cudaEventCreateWithFlags(&g_evFork, cudaEventDisableTiming);
        cudaEventCreateWithFlags(&g_evScan, cudaEventDisableTiming);
        cudaEventCreateWithFlags(&g_evFill, cudaEventDisableTiming);
    }

    float*  d_x  = nullptr; cudaGetSymbolAddress((void**)&d_x,  g_x);
    __half* d_xw = nullptr; cudaGetSymbolAddress((void**)&d_xw, g_xwh);
    uint*   d_WpF = nullptr; cudaGetSymbolAddress((void**)&d_WpF, g_WpF);
    uint*   d_WgF = nullptr; cudaGetSymbolAddress((void**)&d_WgF, g_WgF);

    // ---- fork immediately: CSR chain fully independent of fragment prep ----
    cudaEventRecord(g_evFork, 0);
    cudaStreamWaitEvent(g_s1, g_evFork, 0);

    zero_cnt_k<<<(NN + 255) / 256, 256, 0, g_s1>>>();
    count_k<<<EB4, 256, 0, g_s1>>>(dst);
    scan_k<<<1, 1024, 0, g_s1>>>();
    cudaEventRecord(g_evScan, g_s1);
    fill_k<<<EB4, 256, 0, g_s1>>>(src, dst);
    cudaEventRecord(g_evFill, g_s1);

    prep_k<<<PB, 256>>>(pW, gW);
    mma_gemm_k<LLM, LLM, true><<<MB, 256>>>(llm, d_WpF, pb, ids, emb, d_x, nullptr);

    cudaStreamWaitEvent(0, g_evScan, 0);
    mma_gemm_k<HID, HID, false><<<MB, 256>>>(d_x, d_WgF, nullptr, nullptr, nullptr,
                                             nullptr, d_xw);
    cudaStreamWaitEvent(0, g_evFill, 0);
    agg_k<false><<<HB, 256>>>(gb, nullptr, nullptr, nullptr);

    mma_gemm_k<HID, HID, false><<<MB, 256>>>(d_x, d_WgF + GCN_FRAG_WORDS, nullptr,
                                             nullptr, nullptr, nullptr, d_xw);
    agg_k<true><<<HB, 256>>>(gb + HID, lg, lb, (float*)d_out);
}